// round 1
// baseline (speedup 1.0000x reference)
#include <cuda_runtime.h>
#include <cuda_bf16.h>
#include <math.h>

// ---------------- Problem constants ----------------
#define Bz   1024
#define Nt   31
#define Dm   576
#define Hh   16
#define Ll   12
#define DH   36          // Dm / Hh
#define FF   2304        // 4 * Dm
#define NC   1000
#define EPSV 1e-5f
#define NEGV -987654321.0f
#define RROWS (Bz * Nt) // 31744

// ---------------- Scratch (static device globals; no allocation) ----------------
__device__ float g_h  [(size_t)RROWS * Dm];        // residual stream
__device__ float g_y  [(size_t)RROWS * Dm];        // LN output
__device__ float g_qkv[(size_t)RROWS * 3 * Dm];    // qkv projections
__device__ float g_o  [(size_t)RROWS * Dm];        // attention output
__device__ float g_m  [(size_t)RROWS * FF];        // MLP hidden
__device__ float g_cls[(size_t)Bz * Dm];           // final-LN'd cls tokens

// ---------------- LayerNorm: one warp per row, two-pass variance ----------------
// in_row_stride lets us pick strided rows (cls tokens) for the final LN.
__global__ void ln_kernel(const float* __restrict__ x,
                          const float* __restrict__ w,
                          const float* __restrict__ b,
                          float* __restrict__ y,
                          int rows, long long in_row_stride) {
    int row = blockIdx.x * (blockDim.x >> 5) + (threadIdx.x >> 5);
    if (row >= rows) return;
    int lane = threadIdx.x & 31;
    const float* xr = x + (long long)row * in_row_stride;
    float v[18];
    float s = 0.f;
#pragma unroll
    for (int i = 0; i < 18; i++) { v[i] = xr[lane + i * 32]; s += v[i]; }
#pragma unroll
    for (int o = 16; o; o >>= 1) s += __shfl_xor_sync(0xffffffffu, s, o);
    float mean = s * (1.0f / Dm);
    float s2 = 0.f;
#pragma unroll
    for (int i = 0; i < 18; i++) { float d = v[i] - mean; s2 += d * d; }
#pragma unroll
    for (int o = 16; o; o >>= 1) s2 += __shfl_xor_sync(0xffffffffu, s2, o);
    float inv = rsqrtf(s2 * (1.0f / Dm) + EPSV);
    float* yr = y + (long long)row * Dm;
#pragma unroll
    for (int i = 0; i < 18; i++) {
        int d = lane + i * 32;
        yr[d] = (v[i] - mean) * inv * w[d] + b[d];
    }
}

// ---------------- Attention: one block per (batch, head) ----------------
__global__ void attn_kernel(const float* __restrict__ qkv,
                            const float* __restrict__ scale, // per-head, layer-offset
                            float* __restrict__ o) {
    int b = blockIdx.x;
    int h = blockIdx.y;
    __shared__ float qs[Nt][DH];
    __shared__ float ks[Nt][DH];
    __shared__ float vs[Nt][DH];
    __shared__ float ss[Nt][32];
    int tid = threadIdx.x; // 128 threads
    const float* base = qkv + (long long)b * Nt * (3 * Dm) + h * DH;
    for (int idx = tid; idx < Nt * DH; idx += blockDim.x) {
        int n = idx / DH, d = idx % DH;
        const float* p = base + (long long)n * (3 * Dm);
        qs[n][d] = p[d];
        ks[n][d] = p[Dm + d];
        vs[n][d] = p[2 * Dm + d];
    }
    __syncthreads();
    float sc = scale[h];
    for (int idx = tid; idx < Nt * Nt; idx += blockDim.x) {
        int i = idx / Nt, j = idx % Nt;
        if (i == j) { ss[i][j] = NEGV; continue; }
        float acc = 0.f;
#pragma unroll
        for (int d = 0; d < DH; d++) acc += qs[i][d] * ks[j][d];
        ss[i][j] = acc * sc;
    }
    __syncthreads();
    if (tid < Nt) {
        int i = tid;
        float mx = -3.4e38f;
#pragma unroll
        for (int j = 0; j < Nt; j++) mx = fmaxf(mx, ss[i][j]);
        float sum = 0.f;
#pragma unroll
        for (int j = 0; j < Nt; j++) { float e = expf(ss[i][j] - mx); ss[i][j] = e; sum += e; }
        float invs = 1.0f / sum;
#pragma unroll
        for (int j = 0; j < Nt; j++) ss[i][j] *= invs;
    }
    __syncthreads();
    for (int idx = tid; idx < Nt * DH; idx += blockDim.x) {
        int i = idx / DH, d = idx % DH;
        float acc = 0.f;
#pragma unroll
        for (int j = 0; j < Nt; j++) acc += ss[i][j] * vs[j][d];
        o[(long long)(b * Nt + i) * Dm + h * DH + d] = acc;
    }
}

// ---------------- SGEMM (NT): C[M,Nout] = A[M,K] * W[Nout,K]^T (+bias)(gelu)(+res) ---
// Requirements: M % 128 == 0, K % 8 == 0, K % 4 == 0. Nout guarded.
#define BM 128
#define BN 64
#define BK 8

__device__ __forceinline__ float gelu_exact(float x) {
    return 0.5f * x * (1.0f + erff(x * 0.70710678118654752f));
}

template <bool BIAS, bool RES, bool GELU>
__global__ __launch_bounds__(256) void sgemm_nt(
    const float* __restrict__ A, const float* __restrict__ W,
    const float* __restrict__ bias, const float* __restrict__ res,
    float* __restrict__ C, int M, int Nout, int K) {
    __shared__ float As[BK][BM];
    __shared__ float Ws[BK][BN];
    int t = threadIdx.x;
    int m0 = blockIdx.y * BM;
    int n0 = blockIdx.x * BN;

    int ra = t >> 1;            // 0..127
    int ca = (t & 1) * 4;       // 0 or 4
    int rw = (t & 127) >> 1;    // 0..63
    int cw = (t & 1) * 4;

    int ty = t >> 4;            // 0..15 -> m
    int tx = t & 15;            // 0..15 -> n

    float acc[8][4];
#pragma unroll
    for (int i = 0; i < 8; i++)
#pragma unroll
        for (int j = 0; j < 4; j++) acc[i][j] = 0.f;

    const float* Aptr = A + (long long)(m0 + ra) * K + ca;
    const float* Wptr = W + (long long)(n0 + rw) * K + cw;
    bool wvalid = (n0 + rw) < Nout;

    for (int k0 = 0; k0 < K; k0 += BK) {
        float4 av = *(const float4*)(Aptr + k0);
        As[ca + 0][ra] = av.x;
        As[ca + 1][ra] = av.y;
        As[ca + 2][ra] = av.z;
        As[ca + 3][ra] = av.w;
        if (t < 128) {
            float4 wv = make_float4(0.f, 0.f, 0.f, 0.f);
            if (wvalid) wv = *(const float4*)(Wptr + k0);
            Ws[cw + 0][rw] = wv.x;
            Ws[cw + 1][rw] = wv.y;
            Ws[cw + 2][rw] = wv.z;
            Ws[cw + 3][rw] = wv.w;
        }
        __syncthreads();
#pragma unroll
        for (int k = 0; k < BK; k++) {
            float a[8], bb[4];
#pragma unroll
            for (int i = 0; i < 8; i++) a[i] = As[k][ty * 8 + i];
#pragma unroll
            for (int j = 0; j < 4; j++) bb[j] = Ws[k][tx * 4 + j];
#pragma unroll
            for (int i = 0; i < 8; i++)
#pragma unroll
                for (int j = 0; j < 4; j++) acc[i][j] = fmaf(a[i], bb[j], acc[i][j]);
        }
        __syncthreads();
    }

#pragma unroll
    for (int i = 0; i < 8; i++) {
        long long m = m0 + ty * 8 + i;
#pragma unroll
        for (int j = 0; j < 4; j++) {
            int n = n0 + tx * 4 + j;
            if (n < Nout) {
                float v = acc[i][j];
                if (BIAS) v += bias[n];
                if (GELU) v = gelu_exact(v);
                if (RES) v += res[m * Nout + n];
                C[m * Nout + n] = v;
            }
        }
    }
}

// ---------------- Host launcher ----------------
extern "C" void kernel_launch(void* const* d_in, const int* in_sizes, int n_in,
                              void* d_out, int out_size) {
    const float* x      = (const float*)d_in[0];
    const float* qkv_w  = (const float*)d_in[1];
    const float* scale  = (const float*)d_in[2];
    const float* out_w  = (const float*)d_in[3];
    const float* out_b  = (const float*)d_in[4];
    const float* ln1_w  = (const float*)d_in[5];
    const float* ln1_b  = (const float*)d_in[6];
    const float* ln2_w  = (const float*)d_in[7];
    const float* ln2_b  = (const float*)d_in[8];
    const float* fc1_w  = (const float*)d_in[9];
    const float* fc1_b  = (const float*)d_in[10];
    const float* fc2_w  = (const float*)d_in[11];
    const float* fc2_b  = (const float*)d_in[12];
    const float* norm_w = (const float*)d_in[13];
    const float* norm_b = (const float*)d_in[14];
    const float* head_w = (const float*)d_in[15];
    const float* head_b = (const float*)d_in[16];
    float* out = (float*)d_out;

    float *h, *y, *qkv, *o, *m, *cls;
    cudaGetSymbolAddress((void**)&h,   g_h);
    cudaGetSymbolAddress((void**)&y,   g_y);
    cudaGetSymbolAddress((void**)&qkv, g_qkv);
    cudaGetSymbolAddress((void**)&o,   g_o);
    cudaGetSymbolAddress((void**)&m,   g_m);
    cudaGetSymbolAddress((void**)&cls, g_cls);

    cudaMemcpyAsync(h, x, sizeof(float) * (size_t)RROWS * Dm, cudaMemcpyDeviceToDevice);

    dim3 gQKV(3 * Dm / BN, RROWS / BM);
    dim3 gPROJ(Dm / BN, RROWS / BM);
    dim3 gFC1(FF / BN, RROWS / BM);
    dim3 gATT(Bz, Hh);
    int lnBlocks = RROWS / 8; // 8 warps/block

    for (int l = 0; l < Ll; l++) {
        const float* qw = qkv_w + (size_t)l * 3 * Dm * Dm;
        const float* ow = out_w + (size_t)l * Dm * Dm;
        const float* w1 = fc1_w + (size_t)l * FF * Dm;
        const float* w2 = fc2_w + (size_t)l * Dm * FF;

        ln_kernel<<<lnBlocks, 256>>>(h, ln1_w + l * Dm, ln1_b + l * Dm, y, RROWS, Dm);
        sgemm_nt<false, false, false><<<gQKV, 256>>>(y, qw, nullptr, nullptr, qkv,
                                                     RROWS, 3 * Dm, Dm);
        attn_kernel<<<gATT, 128>>>(qkv, scale + l * Hh, o);
        sgemm_nt<true, true, false><<<gPROJ, 256>>>(o, ow, out_b + l * Dm, h, h,
                                                    RROWS, Dm, Dm);
        ln_kernel<<<lnBlocks, 256>>>(h, ln2_w + l * Dm, ln2_b + l * Dm, y, RROWS, Dm);
        sgemm_nt<true, false, true><<<gFC1, 256>>>(y, w1, fc1_b + l * FF, nullptr, m,
                                                   RROWS, FF, Dm);
        sgemm_nt<true, true, false><<<gPROJ, 256>>>(m, w2, fc2_b + l * Dm, h, h,
                                                    RROWS, Dm, FF);
    }

    // Final LN on cls tokens only (row n==0 of each batch element), then head.
    ln_kernel<<<Bz / 8, 256>>>(h, norm_w, norm_b, cls, Bz, (long long)Nt * Dm);
    dim3 gHEAD((NC + BN - 1) / BN, Bz / BM);
    sgemm_nt<true, false, false><<<gHEAD, 256>>>(cls, head_w, head_b, nullptr, out,
                                                 Bz, NC, Dm);
}

// round 4
// speedup vs baseline: 4.5188x; 4.5188x over previous
#include <cuda_runtime.h>
#include <cuda_fp16.h>
#include <math.h>
#include <stdint.h>

// ---------------- Problem constants ----------------
#define Bz   1024
#define Nt   31
#define Dm   576
#define Hh   16
#define Ll   12
#define DH   36
#define FF   2304
#define NC   1000
#define EPSV 1e-5f
#define NEGV -987654321.0f
#define RROWS (Bz * Nt) // 31744

// ---------------- Scratch ----------------
__device__ float  g_h  [(size_t)RROWS * Dm];
__device__ __half g_y  [(size_t)RROWS * Dm];
__device__ __half g_qkv[(size_t)RROWS * 3 * Dm];
__device__ __half g_o  [(size_t)RROWS * Dm];
__device__ __half g_m  [(size_t)RROWS * FF];
__device__ __half g_cls[(size_t)Bz * Dm];

// fp16 weight arena
#define OQKV  0
#define OOUT  11943936
#define OFC1  15925248
#define OFC2  31850496
#define OHEAD 47775744
#define WTOT  48351744
__device__ __half g_w16[WTOT];

// ---------------- helpers ----------------
__device__ __forceinline__ uint32_t cvta_smem(const void* p) {
    uint32_t a;
    asm("{ .reg .u64 t; cvta.to.shared.u64 t, %1; cvt.u32.u64 %0, t; }" : "=r"(a) : "l"(p));
    return a;
}
__device__ __forceinline__ void cpasync16(uint32_t dst, const void* src, uint32_t srcsize) {
    asm volatile("cp.async.cg.shared.global [%0], [%1], 16, %2;"
                 :: "r"(dst), "l"(src), "r"(srcsize));
}
__device__ __forceinline__ void ldmA(uint32_t* a, uint32_t addr) {
    asm volatile("ldmatrix.sync.aligned.m8n8.x4.shared.b16 {%0,%1,%2,%3}, [%4];"
                 : "=r"(a[0]), "=r"(a[1]), "=r"(a[2]), "=r"(a[3]) : "r"(addr));
}
__device__ __forceinline__ void ldmB(uint32_t* b, uint32_t addr) {
    asm volatile("ldmatrix.sync.aligned.m8n8.x2.shared.b16 {%0,%1}, [%2];"
                 : "=r"(b[0]), "=r"(b[1]) : "r"(addr));
}
__device__ __forceinline__ void mma16816(float* c, const uint32_t* a, const uint32_t* b) {
    asm volatile(
        "mma.sync.aligned.m16n8k16.row.col.f32.f16.f16.f32 "
        "{%0,%1,%2,%3}, {%4,%5,%6,%7}, {%8,%9}, {%0,%1,%2,%3};"
        : "+f"(c[0]), "+f"(c[1]), "+f"(c[2]), "+f"(c[3])
        : "r"(a[0]), "r"(a[1]), "r"(a[2]), "r"(a[3]), "r"(b[0]), "r"(b[1]));
}
__device__ __forceinline__ float gelu_exact(float x) {
    return 0.5f * x * (1.0f + erff(x * 0.70710678118654752f));
}

// ---------------- convert fp32 -> fp16 ----------------
__global__ void f32half(const float* __restrict__ s, __half* __restrict__ d, int n) {
    int i = blockIdx.x * blockDim.x + threadIdx.x;
    int st = gridDim.x * blockDim.x;
    for (; i < n; i += st) d[i] = __float2half_rn(s[i]);
}

// ---------------- LayerNorm (fp32 in, fp16 out) ----------------
__global__ void ln_kernel(const float* __restrict__ x,
                          const float* __restrict__ w,
                          const float* __restrict__ b,
                          __half* __restrict__ y,
                          int rows, long long in_row_stride) {
    int row = blockIdx.x * (blockDim.x >> 5) + (threadIdx.x >> 5);
    if (row >= rows) return;
    int lane = threadIdx.x & 31;
    const float* xr = x + (long long)row * in_row_stride;
    float v[18];
    float s = 0.f;
#pragma unroll
    for (int i = 0; i < 18; i++) { v[i] = xr[lane + i * 32]; s += v[i]; }
#pragma unroll
    for (int o = 16; o; o >>= 1) s += __shfl_xor_sync(0xffffffffu, s, o);
    float mean = s * (1.0f / Dm);
    float s2 = 0.f;
#pragma unroll
    for (int i = 0; i < 18; i++) { float d = v[i] - mean; s2 += d * d; }
#pragma unroll
    for (int o = 16; o; o >>= 1) s2 += __shfl_xor_sync(0xffffffffu, s2, o);
    float inv = rsqrtf(s2 * (1.0f / Dm) + EPSV);
    __half* yr = y + (long long)row * Dm;
#pragma unroll
    for (int i = 0; i < 18; i++) {
        int d = lane + i * 32;
        yr[d] = __float2half_rn((v[i] - mean) * inv * w[d] + b[d]);
    }
}

// ---------------- Attention: one block per (batch, head), fp16 io ----------------
__global__ void attn_kernel(const __half* __restrict__ qkv,
                            const float* __restrict__ scale,
                            __half* __restrict__ o) {
    int b = blockIdx.x;
    int h = blockIdx.y;
    __shared__ float qs[Nt][DH];
    __shared__ float ks[Nt][DH];
    __shared__ float vs[Nt][DH];
    __shared__ float ss[Nt][32];
    int tid = threadIdx.x; // 128
    const __half* base = qkv + (long long)b * Nt * (3 * Dm) + h * DH;
    for (int idx = tid; idx < Nt * DH; idx += blockDim.x) {
        int n = idx / DH, d = idx % DH;
        const __half* p = base + (long long)n * (3 * Dm);
        qs[n][d] = __half2float(p[d]);
        ks[n][d] = __half2float(p[Dm + d]);
        vs[n][d] = __half2float(p[2 * Dm + d]);
    }
    __syncthreads();
    float sc = scale[h];
    for (int idx = tid; idx < Nt * Nt; idx += blockDim.x) {
        int i = idx / Nt, j = idx % Nt;
        if (i == j) { ss[i][j] = NEGV; continue; }
        float acc = 0.f;
#pragma unroll
        for (int d = 0; d < DH; d++) acc += qs[i][d] * ks[j][d];
        ss[i][j] = acc * sc;
    }
    __syncthreads();
    if (tid < Nt) {
        int i = tid;
        float mx = -3.4e38f;
#pragma unroll
        for (int j = 0; j < Nt; j++) mx = fmaxf(mx, ss[i][j]);
        float sum = 0.f;
#pragma unroll
        for (int j = 0; j < Nt; j++) { float e = expf(ss[i][j] - mx); ss[i][j] = e; sum += e; }
        float invs = 1.0f / sum;
#pragma unroll
        for (int j = 0; j < Nt; j++) ss[i][j] *= invs;
    }
    __syncthreads();
    for (int idx = tid; idx < Nt * DH; idx += blockDim.x) {
        int i = idx / DH, d = idx % DH;
        float acc = 0.f;
#pragma unroll
        for (int j = 0; j < Nt; j++) acc += ss[i][j] * vs[j][d];
        o[(long long)(b * Nt + i) * Dm + h * DH + d] = __float2half_rn(acc);
    }
}

// ---------------- HMMA GEMM: C[M,Nout] = A[M,K] * W[Nout,K]^T ----------------
// BM=128, BN=64, BK=32, 3-stage cp.async pipeline, 8 warps (4m x 2n), warp tile 32x32.
#define BM 128
#define BN 64
#define BK 32
#define STG 3
#define APAD 40   // halfs per smem row (32 data + 8 pad) -> 80B stride, conflict-free

template <bool NG>
__device__ __forceinline__ void load_tile(const __half* A, const __half* W,
                                          int Nout, int K, int m0, int n0, int k0,
                                          uint32_t sa, uint32_t sb, int tid) {
    // A: 128 rows x 4 chunks(16B) = 512 chunks
#pragma unroll
    for (int i = 0; i < 2; i++) {
        int idx = tid + i * 256;
        int r = idx >> 2, ch = idx & 3;
        const __half* g = A + (size_t)(m0 + r) * K + k0 + ch * 8;
        cpasync16(sa + r * (APAD * 2) + ch * 16, g, 16);
    }
    // B: 64 rows x 4 chunks = 256 chunks
    {
        int r = tid >> 2, ch = tid & 3;
        int rr = n0 + r;
        uint32_t sz = 16;
        if (NG && rr >= Nout) { rr = 0; sz = 0; }
        const __half* g = W + (size_t)rr * K + k0 + ch * 8;
        cpasync16(sb + r * (APAD * 2) + ch * 16, g, sz);
    }
    asm volatile("cp.async.commit_group;" ::: "memory");
}

template <bool BIAS, bool RES, bool GELU, bool HALFOUT, bool NG>
__global__ __launch_bounds__(256) void hgemm(
    const __half* __restrict__ A, const __half* __restrict__ W,
    const float* __restrict__ bias, const float* __restrict__ resid,
    void* __restrict__ Cout, int M, int Nout, int K) {
    __shared__ __half As[STG][BM][APAD];
    __shared__ __half Bs[STG][BN][APAD];
    int tid = threadIdx.x, wid = tid >> 5, lane = tid & 31;
    int wm = wid >> 1, wn = wid & 1;
    int m0 = blockIdx.y * BM, n0 = blockIdx.x * BN;

    uint32_t sA[STG], sB[STG];
#pragma unroll
    for (int s = 0; s < STG; s++) {
        sA[s] = cvta_smem(&As[s][0][0]);
        sB[s] = cvta_smem(&Bs[s][0][0]);
    }

    float c[2][4][4];
#pragma unroll
    for (int mi = 0; mi < 2; mi++)
#pragma unroll
        for (int ni = 0; ni < 4; ni++)
#pragma unroll
            for (int j = 0; j < 4; j++) c[mi][ni][j] = 0.f;

    const int T = K / BK;
    // prologue: stages 0, 1
    load_tile<NG>(A, W, Nout, K, m0, n0, 0,  sA[0], sB[0], tid);
    load_tile<NG>(A, W, Nout, K, m0, n0, BK, sA[1], sB[1], tid);

    // per-warp ldmatrix address components
    int la16 = lane & 15;
    uint32_t aRow = (uint32_t)(wm * 32 + la16);          // + mi*16
    uint32_t aCol8 = (uint32_t)((lane >> 4) * 8);        // + ks*16
    uint32_t bRow = (uint32_t)(wn * 32 + (la16 & 7));    // + ni*8
    uint32_t bCol8 = (uint32_t)(((la16 >> 3) & 1) * 8);  // + ks*16

    for (int t = 0; t < T; t++) {
        asm volatile("cp.async.wait_group %0;" :: "n"(STG - 2) : "memory");
        __syncthreads();
        if (t + STG - 1 < T) {
            load_tile<NG>(A, W, Nout, K, m0, n0, (t + STG - 1) * BK,
                          sA[(t + STG - 1) % STG], sB[(t + STG - 1) % STG], tid);
        } else {
            asm volatile("cp.async.commit_group;" ::: "memory");
        }
        int s = t % STG;
#pragma unroll
        for (int ks = 0; ks < 2; ks++) {
            uint32_t a[2][4], b[4][2];
#pragma unroll
            for (int mi = 0; mi < 2; mi++)
                ldmA(a[mi], sA[s] + ((aRow + mi * 16) * APAD + ks * 16 + aCol8) * 2);
#pragma unroll
            for (int ni = 0; ni < 4; ni++)
                ldmB(b[ni], sB[s] + ((bRow + ni * 8) * APAD + ks * 16 + bCol8) * 2);
#pragma unroll
            for (int mi = 0; mi < 2; mi++)
#pragma unroll
                for (int ni = 0; ni < 4; ni++)
                    mma16816(c[mi][ni], a[mi], b[ni]);
        }
        __syncthreads();
    }

    // epilogue
    int rbase = m0 + wm * 32 + (lane >> 2);
    int cbase = n0 + wn * 32 + (lane & 3) * 2;
#pragma unroll
    for (int mi = 0; mi < 2; mi++) {
#pragma unroll
        for (int half = 0; half < 2; half++) {
            size_t row = (size_t)(rbase + mi * 16 + half * 8);
#pragma unroll
            for (int ni = 0; ni < 4; ni++) {
                int col = cbase + ni * 8;
                if (!NG || col + 1 < Nout) {
                    float v0 = c[mi][ni][half * 2 + 0];
                    float v1 = c[mi][ni][half * 2 + 1];
                    if (BIAS) { v0 += bias[col]; v1 += bias[col + 1]; }
                    if (GELU) { v0 = gelu_exact(v0); v1 = gelu_exact(v1); }
                    if (RES) {
                        v0 += resid[row * Nout + col];
                        v1 += resid[row * Nout + col + 1];
                    }
                    if (HALFOUT) {
                        *(__half2*)((__half*)Cout + row * Nout + col) =
                            __floats2half2_rn(v0, v1);
                    } else {
                        *(float2*)((float*)Cout + row * Nout + col) =
                            make_float2(v0, v1);
                    }
                }
            }
        }
    }
}

// ---------------- Host launcher ----------------
extern "C" void kernel_launch(void* const* d_in, const int* in_sizes, int n_in,
                              void* d_out, int out_size) {
    const float* x      = (const float*)d_in[0];
    const float* qkv_w  = (const float*)d_in[1];
    const float* scale  = (const float*)d_in[2];
    const float* out_w  = (const float*)d_in[3];
    const float* out_b  = (const float*)d_in[4];
    const float* ln1_w  = (const float*)d_in[5];
    const float* ln1_b  = (const float*)d_in[6];
    const float* ln2_w  = (const float*)d_in[7];
    const float* ln2_b  = (const float*)d_in[8];
    const float* fc1_w  = (const float*)d_in[9];
    const float* fc1_b  = (const float*)d_in[10];
    const float* fc2_w  = (const float*)d_in[11];
    const float* fc2_b  = (const float*)d_in[12];
    const float* norm_w = (const float*)d_in[13];
    const float* norm_b = (const float*)d_in[14];
    const float* head_w = (const float*)d_in[15];
    const float* head_b = (const float*)d_in[16];
    float* out = (float*)d_out;

    float  *h;
    __half *y, *qkv, *o, *m, *cls, *w16;
    cudaGetSymbolAddress((void**)&h,   g_h);
    cudaGetSymbolAddress((void**)&y,   g_y);
    cudaGetSymbolAddress((void**)&qkv, g_qkv);
    cudaGetSymbolAddress((void**)&o,   g_o);
    cudaGetSymbolAddress((void**)&m,   g_m);
    cudaGetSymbolAddress((void**)&cls, g_cls);
    cudaGetSymbolAddress((void**)&w16, g_w16);

    cudaMemcpyAsync(h, x, sizeof(float) * (size_t)RROWS * Dm, cudaMemcpyDeviceToDevice);

    // convert weights to fp16 once per replay
    f32half<<<512, 256>>>(qkv_w,  w16 + OQKV,  11943936);
    f32half<<<512, 256>>>(out_w,  w16 + OOUT,  3981312);
    f32half<<<512, 256>>>(fc1_w,  w16 + OFC1,  15925248);
    f32half<<<512, 256>>>(fc2_w,  w16 + OFC2,  15925248);
    f32half<<<64,  256>>>(head_w, w16 + OHEAD, 576000);

    dim3 gQKV(3 * Dm / BN, RROWS / BM);   // (27, 248)
    dim3 gPROJ(Dm / BN, RROWS / BM);      // (9, 248)
    dim3 gFC1(FF / BN, RROWS / BM);       // (36, 248)
    dim3 gATT(Bz, Hh);
    int lnBlocks = RROWS / 8;

    for (int l = 0; l < Ll; l++) {
        const __half* qw = w16 + OQKV + (size_t)l * 3 * Dm * Dm;
        const __half* ow = w16 + OOUT + (size_t)l * Dm * Dm;
        const __half* w1 = w16 + OFC1 + (size_t)l * FF * Dm;
        const __half* w2 = w16 + OFC2 + (size_t)l * Dm * FF;

        ln_kernel<<<lnBlocks, 256>>>(h, ln1_w + l * Dm, ln1_b + l * Dm, y, RROWS, Dm);
        hgemm<false, false, false, true, false><<<gQKV, 256>>>(
            y, qw, nullptr, nullptr, qkv, RROWS, 3 * Dm, Dm);
        attn_kernel<<<gATT, 128>>>(qkv, scale + l * Hh, o);
        hgemm<true, true, false, false, false><<<gPROJ, 256>>>(
            o, ow, out_b + l * Dm, h, h, RROWS, Dm, Dm);
        ln_kernel<<<lnBlocks, 256>>>(h, ln2_w + l * Dm, ln2_b + l * Dm, y, RROWS, Dm);
        hgemm<true, false, true, true, false><<<gFC1, 256>>>(
            y, w1, fc1_b + l * FF, nullptr, m, RROWS, FF, Dm);
        hgemm<true, true, false, false, false><<<gPROJ, 256>>>(
            m, w2, fc2_b + l * Dm, h, h, RROWS, Dm, FF);
    }

    // final LN on cls tokens, then classifier head
    ln_kernel<<<Bz / 8, 256>>>(h, norm_w, norm_b, cls, Bz, (long long)Nt * Dm);
    dim3 gHEAD((NC + BN - 1) / BN, Bz / BM); // (16, 8)
    hgemm<true, false, false, false, true><<<gHEAD, 256>>>(
        cls, w16 + OHEAD, head_b, nullptr, out, Bz, NC, Dm);
}

// round 5
// speedup vs baseline: 4.8400x; 1.0711x over previous
#include <cuda_runtime.h>
#include <cuda_fp16.h>
#include <math.h>
#include <stdint.h>

// ---------------- Problem constants ----------------
#define Bz   1024
#define Nt   31
#define Dm   576
#define Hh   16
#define Ll   12
#define DH   36
#define FF   2304
#define NC   1000
#define EPSV 1e-5f
#define NEGV -987654321.0f
#define RROWS (Bz * Nt) // 31744

// ---------------- Scratch ----------------
__device__ float  g_h  [(size_t)RROWS * Dm];
__device__ __half g_y  [(size_t)RROWS * Dm];
__device__ __half g_qkv[(size_t)RROWS * 3 * Dm];
__device__ __half g_o  [(size_t)RROWS * Dm];
__device__ __half g_m  [(size_t)RROWS * FF];
__device__ __half g_cls[(size_t)Bz * Dm];

// fp16 weight arena
#define OQKV  0
#define OOUT  11943936
#define OFC1  15925248
#define OFC2  31850496
#define OHEAD 47775744
#define WTOT  48351744
__device__ __half g_w16[WTOT];

// ---------------- helpers ----------------
__device__ __forceinline__ uint32_t cvta_smem(const void* p) {
    uint32_t a;
    asm("{ .reg .u64 t; cvta.to.shared.u64 t, %1; cvt.u32.u64 %0, t; }" : "=r"(a) : "l"(p));
    return a;
}
__device__ __forceinline__ void cpasync16(uint32_t dst, const void* src, uint32_t srcsize) {
    asm volatile("cp.async.cg.shared.global [%0], [%1], 16, %2;"
                 :: "r"(dst), "l"(src), "r"(srcsize));
}
__device__ __forceinline__ void ldm4(uint32_t* a, uint32_t addr) {
    asm volatile("ldmatrix.sync.aligned.m8n8.x4.shared.b16 {%0,%1,%2,%3}, [%4];"
                 : "=r"(a[0]), "=r"(a[1]), "=r"(a[2]), "=r"(a[3]) : "r"(addr));
}
__device__ __forceinline__ void mma16816(float* c, const uint32_t* a, const uint32_t* b) {
    asm volatile(
        "mma.sync.aligned.m16n8k16.row.col.f32.f16.f16.f32 "
        "{%0,%1,%2,%3}, {%4,%5,%6,%7}, {%8,%9}, {%0,%1,%2,%3};"
        : "+f"(c[0]), "+f"(c[1]), "+f"(c[2]), "+f"(c[3])
        : "r"(a[0]), "r"(a[1]), "r"(a[2]), "r"(a[3]), "r"(b[0]), "r"(b[1]));
}
__device__ __forceinline__ float gelu_exact(float x) {
    return 0.5f * x * (1.0f + erff(x * 0.70710678118654752f));
}

// ---------------- convert fp32 -> fp16 ----------------
__global__ void f32half(const float* __restrict__ s, __half* __restrict__ d, int n) {
    int i = blockIdx.x * blockDim.x + threadIdx.x;
    int st = gridDim.x * blockDim.x;
    for (; i < n; i += st) d[i] = __float2half_rn(s[i]);
}

// ---------------- LayerNorm (fp32 in, fp16 out) ----------------
__global__ void ln_kernel(const float* __restrict__ x,
                          const float* __restrict__ w,
                          const float* __restrict__ b,
                          __half* __restrict__ y,
                          int rows, long long in_row_stride) {
    int row = blockIdx.x * (blockDim.x >> 5) + (threadIdx.x >> 5);
    if (row >= rows) return;
    int lane = threadIdx.x & 31;
    const float* xr = x + (long long)row * in_row_stride;
    float v[18];
    float s = 0.f;
#pragma unroll
    for (int i = 0; i < 18; i++) { v[i] = xr[lane + i * 32]; s += v[i]; }
#pragma unroll
    for (int o = 16; o; o >>= 1) s += __shfl_xor_sync(0xffffffffu, s, o);
    float mean = s * (1.0f / Dm);
    float s2 = 0.f;
#pragma unroll
    for (int i = 0; i < 18; i++) { float d = v[i] - mean; s2 += d * d; }
#pragma unroll
    for (int o = 16; o; o >>= 1) s2 += __shfl_xor_sync(0xffffffffu, s2, o);
    float inv = rsqrtf(s2 * (1.0f / Dm) + EPSV);
    __half* yr = y + (long long)row * Dm;
#pragma unroll
    for (int i = 0; i < 18; i++) {
        int d = lane + i * 32;
        yr[d] = __float2half_rn((v[i] - mean) * inv * w[d] + b[d]);
    }
}

// ---------------- Attention: one block per (batch, head), fp16 io ----------------
__global__ void attn_kernel(const __half* __restrict__ qkv,
                            const float* __restrict__ scale,
                            __half* __restrict__ o) {
    int b = blockIdx.x;
    int h = blockIdx.y;
    __shared__ float qs[Nt][DH];
    __shared__ float ks[Nt][DH];
    __shared__ float vs[Nt][DH];
    __shared__ float ss[Nt][32];
    int tid = threadIdx.x; // 128
    const __half* base = qkv + (long long)b * Nt * (3 * Dm) + h * DH;
    for (int idx = tid; idx < Nt * DH; idx += blockDim.x) {
        int n = idx / DH, d = idx % DH;
        const __half* p = base + (long long)n * (3 * Dm);
        qs[n][d] = __half2float(p[d]);
        ks[n][d] = __half2float(p[Dm + d]);
        vs[n][d] = __half2float(p[2 * Dm + d]);
    }
    __syncthreads();
    float sc = scale[h];
    for (int idx = tid; idx < Nt * Nt; idx += blockDim.x) {
        int i = idx / Nt, j = idx % Nt;
        if (i == j) { ss[i][j] = NEGV; continue; }
        float acc = 0.f;
#pragma unroll
        for (int d = 0; d < DH; d++) acc += qs[i][d] * ks[j][d];
        ss[i][j] = acc * sc;
    }
    __syncthreads();
    if (tid < Nt) {
        int i = tid;
        float mx = -3.4e38f;
#pragma unroll
        for (int j = 0; j < Nt; j++) mx = fmaxf(mx, ss[i][j]);
        float sum = 0.f;
#pragma unroll
        for (int j = 0; j < Nt; j++) { float e = expf(ss[i][j] - mx); ss[i][j] = e; sum += e; }
        float invs = 1.0f / sum;
#pragma unroll
        for (int j = 0; j < Nt; j++) ss[i][j] *= invs;
    }
    __syncthreads();
    for (int idx = tid; idx < Nt * DH; idx += blockDim.x) {
        int i = idx / DH, d = idx % DH;
        float acc = 0.f;
#pragma unroll
        for (int j = 0; j < Nt; j++) acc += ss[i][j] * vs[j][d];
        o[(long long)(b * Nt + i) * Dm + h * DH + d] = __float2half_rn(acc);
    }
}

// ---------------- HMMA GEMM: C[M,Nout] = A[M,K] * W[Nout,K]^T ----------------
// BM=128, BN=96, BK=32, 4-stage cp.async pipeline, 8 warps (4m x 2n), warp tile 32x48.
#define BM 128
#define BN 96
#define BK 32
#define STG 4
#define APAD 40   // halfs per smem row (32 data + 8 pad) -> 80B stride

template <bool NG>
__device__ __forceinline__ void load_tile(const __half* A, const __half* W,
                                          int Nout, int K, int m0, int n0, int k0,
                                          uint32_t sa, uint32_t sb, int tid) {
    // A: 128 rows x 4 chunks(16B) = 512 chunks
#pragma unroll
    for (int i = 0; i < 2; i++) {
        int idx = tid + i * 256;
        int r = idx >> 2, ch = idx & 3;
        const __half* g = A + (size_t)(m0 + r) * K + k0 + ch * 8;
        cpasync16(sa + r * (APAD * 2) + ch * 16, g, 16);
    }
    // B: 96 rows x 4 chunks = 384 chunks
#pragma unroll
    for (int i = 0; i < 2; i++) {
        int idx = tid + i * 256;
        if (idx < 384) {
            int r = idx >> 2, ch = idx & 3;
            int rr = n0 + r;
            uint32_t sz = 16;
            if (NG && rr >= Nout) { rr = 0; sz = 0; }
            const __half* g = W + (size_t)rr * K + k0 + ch * 8;
            cpasync16(sb + r * (APAD * 2) + ch * 16, g, sz);
        }
    }
    asm volatile("cp.async.commit_group;" ::: "memory");
}

template <bool BIAS, bool RES, bool GELU, bool HALFOUT, bool NG>
__global__ __launch_bounds__(256) void hgemm(
    const __half* __restrict__ A, const __half* __restrict__ W,
    const float* __restrict__ bias, const float* __restrict__ resid,
    void* __restrict__ Cout, int M, int Nout, int K) {
    __shared__ __half As[STG][BM][APAD];
    __shared__ __half Bs[STG][BN][APAD];
    int tid = threadIdx.x, wid = tid >> 5, lane = tid & 31;
    int wm = wid >> 1, wn = wid & 1;
    int m0 = blockIdx.y * BM, n0 = blockIdx.x * BN;

    uint32_t sA[STG], sB[STG];
#pragma unroll
    for (int s = 0; s < STG; s++) {
        sA[s] = cvta_smem(&As[s][0][0]);
        sB[s] = cvta_smem(&Bs[s][0][0]);
    }

    float c[2][6][4];
#pragma unroll
    for (int mi = 0; mi < 2; mi++)
#pragma unroll
        for (int ni = 0; ni < 6; ni++)
#pragma unroll
            for (int j = 0; j < 4; j++) c[mi][ni][j] = 0.f;

    const int T = K / BK;
#pragma unroll
    for (int p = 0; p < STG - 1; p++)
        load_tile<NG>(A, W, Nout, K, m0, n0, p * BK, sA[p], sB[p], tid);

    // ldmatrix address components
    // A x4: lanes 0-7 rows m0-7 k0, 8-15 rows m8-15 k0, 16-23 m0-7 k8, 24-31 m8-15 k8
    uint32_t aRow = (uint32_t)(wm * 32 + (lane & 15));
    uint32_t aCol8 = (uint32_t)((lane >> 4) * 8);
    // B x4: t=lane>>3: t0 (ni,k0), t1 (ni,k8), t2 (ni+1,k0), t3 (ni+1,k8)
    int t4 = lane >> 3, r8 = lane & 7;
    uint32_t bBase = (uint32_t)((wn * 48 + (t4 >> 1) * 8 + r8) * APAD + (t4 & 1) * 8);

    for (int t = 0; t < T; t++) {
        asm volatile("cp.async.wait_group %0;" :: "n"(STG - 2) : "memory");
        __syncthreads();
        if (t + STG - 1 < T) {
            load_tile<NG>(A, W, Nout, K, m0, n0, (t + STG - 1) * BK,
                          sA[(t + STG - 1) % STG], sB[(t + STG - 1) % STG], tid);
        } else {
            asm volatile("cp.async.commit_group;" ::: "memory");
        }
        int s = t % STG;
#pragma unroll
        for (int ks = 0; ks < 2; ks++) {
            uint32_t a[2][4], b[6][2];
#pragma unroll
            for (int mi = 0; mi < 2; mi++)
                ldm4(a[mi], sA[s] + ((aRow + mi * 16) * APAD + ks * 16 + aCol8) * 2);
#pragma unroll
            for (int nb = 0; nb < 3; nb++) {
                uint32_t bb[4];
                ldm4(bb, sB[s] + (bBase + nb * 16 * APAD + ks * 16) * 2);
                b[nb * 2 + 0][0] = bb[0]; b[nb * 2 + 0][1] = bb[1];
                b[nb * 2 + 1][0] = bb[2]; b[nb * 2 + 1][1] = bb[3];
            }
#pragma unroll
            for (int mi = 0; mi < 2; mi++)
#pragma unroll
                for (int ni = 0; ni < 6; ni++)
                    mma16816(c[mi][ni], a[mi], b[ni]);
        }
        __syncthreads();
    }

    // epilogue
    int rbase = m0 + wm * 32 + (lane >> 2);
    int cbase = n0 + wn * 48 + (lane & 3) * 2;
#pragma unroll
    for (int mi = 0; mi < 2; mi++) {
#pragma unroll
        for (int half = 0; half < 2; half++) {
            size_t row = (size_t)(rbase + mi * 16 + half * 8);
#pragma unroll
            for (int ni = 0; ni < 6; ni++) {
                int col = cbase + ni * 8;
                if (!NG || col + 1 < Nout) {
                    float v0 = c[mi][ni][half * 2 + 0];
                    float v1 = c[mi][ni][half * 2 + 1];
                    if (BIAS) { v0 += bias[col]; v1 += bias[col + 1]; }
                    if (GELU) { v0 = gelu_exact(v0); v1 = gelu_exact(v1); }
                    if (RES) {
                        v0 += resid[row * Nout + col];
                        v1 += resid[row * Nout + col + 1];
                    }
                    if (HALFOUT) {
                        *(__half2*)((__half*)Cout + row * Nout + col) =
                            __floats2half2_rn(v0, v1);
                    } else {
                        *(float2*)((float*)Cout + row * Nout + col) =
                            make_float2(v0, v1);
                    }
                }
            }
        }
    }
}

// ---------------- Host launcher ----------------
extern "C" void kernel_launch(void* const* d_in, const int* in_sizes, int n_in,
                              void* d_out, int out_size) {
    const float* x      = (const float*)d_in[0];
    const float* qkv_w  = (const float*)d_in[1];
    const float* scale  = (const float*)d_in[2];
    const float* out_w  = (const float*)d_in[3];
    const float* out_b  = (const float*)d_in[4];
    const float* ln1_w  = (const float*)d_in[5];
    const float* ln1_b  = (const float*)d_in[6];
    const float* ln2_w  = (const float*)d_in[7];
    const float* ln2_b  = (const float*)d_in[8];
    const float* fc1_w  = (const float*)d_in[9];
    const float* fc1_b  = (const float*)d_in[10];
    const float* fc2_w  = (const float*)d_in[11];
    const float* fc2_b  = (const float*)d_in[12];
    const float* norm_w = (const float*)d_in[13];
    const float* norm_b = (const float*)d_in[14];
    const float* head_w = (const float*)d_in[15];
    const float* head_b = (const float*)d_in[16];
    float* out = (float*)d_out;

    float  *h;
    __half *y, *qkv, *o, *m, *cls, *w16;
    cudaGetSymbolAddress((void**)&h,   g_h);
    cudaGetSymbolAddress((void**)&y,   g_y);
    cudaGetSymbolAddress((void**)&qkv, g_qkv);
    cudaGetSymbolAddress((void**)&o,   g_o);
    cudaGetSymbolAddress((void**)&m,   g_m);
    cudaGetSymbolAddress((void**)&cls, g_cls);
    cudaGetSymbolAddress((void**)&w16, g_w16);

    cudaMemcpyAsync(h, x, sizeof(float) * (size_t)RROWS * Dm, cudaMemcpyDeviceToDevice);

    // convert weights to fp16 once per replay
    f32half<<<512, 256>>>(qkv_w,  w16 + OQKV,  11943936);
    f32half<<<512, 256>>>(out_w,  w16 + OOUT,  3981312);
    f32half<<<512, 256>>>(fc1_w,  w16 + OFC1,  15925248);
    f32half<<<512, 256>>>(fc2_w,  w16 + OFC2,  15925248);
    f32half<<<64,  256>>>(head_w, w16 + OHEAD, 576000);

    dim3 gQKV(3 * Dm / BN, RROWS / BM);   // (18, 248)
    dim3 gPROJ(Dm / BN, RROWS / BM);      // (6, 248)
    dim3 gFC1(FF / BN, RROWS / BM);       // (24, 248)
    dim3 gATT(Bz, Hh);
    int lnBlocks = RROWS / 8;

    for (int l = 0; l < Ll; l++) {
        const __half* qw = w16 + OQKV + (size_t)l * 3 * Dm * Dm;
        const __half* ow = w16 + OOUT + (size_t)l * Dm * Dm;
        const __half* w1 = w16 + OFC1 + (size_t)l * FF * Dm;
        const __half* w2 = w16 + OFC2 + (size_t)l * Dm * FF;

        ln_kernel<<<lnBlocks, 256>>>(h, ln1_w + l * Dm, ln1_b + l * Dm, y, RROWS, Dm);
        hgemm<false, false, false, true, false><<<gQKV, 256>>>(
            y, qw, nullptr, nullptr, qkv, RROWS, 3 * Dm, Dm);
        attn_kernel<<<gATT, 128>>>(qkv, scale + l * Hh, o);
        hgemm<true, true, false, false, false><<<gPROJ, 256>>>(
            o, ow, out_b + l * Dm, h, h, RROWS, Dm, Dm);
        ln_kernel<<<lnBlocks, 256>>>(h, ln2_w + l * Dm, ln2_b + l * Dm, y, RROWS, Dm);
        hgemm<true, false, true, true, false><<<gFC1, 256>>>(
            y, w1, fc1_b + l * FF, nullptr, m, RROWS, FF, Dm);
        hgemm<true, true, false, false, false><<<gPROJ, 256>>>(
            m, w2, fc2_b + l * Dm, h, h, RROWS, Dm, FF);
    }

    // final LN on cls tokens, then classifier head
    ln_kernel<<<Bz / 8, 256>>>(h, norm_w, norm_b, cls, Bz, (long long)Nt * Dm);
    dim3 gHEAD((NC + BN - 1) / BN, Bz / BM); // (11, 8)
    hgemm<true, false, false, false, true><<<gHEAD, 256>>>(
        cls, w16 + OHEAD, head_b, nullptr, out, Bz, NC, Dm);
}

// round 6
// speedup vs baseline: 5.0415x; 1.0416x over previous
#include <cuda_runtime.h>
#include <cuda_fp16.h>
#include <math.h>
#include <stdint.h>

// ---------------- Problem constants ----------------
#define Bz   1024
#define Nt   31
#define Dm   576
#define Hh   16
#define Ll   12
#define DH   36
#define FF   2304
#define NC   1000
#define EPSV 1e-5f
#define NEGV -987654321.0f
#define RROWS (Bz * Nt) // 31744

// ---------------- Scratch ----------------
__device__ float  g_h  [(size_t)RROWS * Dm];
__device__ __half g_y  [(size_t)RROWS * Dm];
__device__ __half g_qkv[(size_t)RROWS * 3 * Dm];
__device__ __half g_o  [(size_t)RROWS * Dm];
__device__ __half g_m  [(size_t)RROWS * FF];
__device__ __half g_cls[(size_t)Bz * Dm];

// fp16 weight arena
#define OQKV  0
#define OOUT  11943936
#define OFC1  15925248
#define OFC2  31850496
#define OHEAD 47775744
#define WTOT  48351744
__device__ __half g_w16[WTOT];

// ---------------- helpers ----------------
__device__ __forceinline__ uint32_t cvta_smem(const void* p) {
    uint32_t a;
    asm("{ .reg .u64 t; cvta.to.shared.u64 t, %1; cvt.u32.u64 %0, t; }" : "=r"(a) : "l"(p));
    return a;
}
__device__ __forceinline__ void cpasync16(uint32_t dst, const void* src, uint32_t srcsize) {
    asm volatile("cp.async.cg.shared.global [%0], [%1], 16, %2;"
                 :: "r"(dst), "l"(src), "r"(srcsize));
}
__device__ __forceinline__ void ldm4(uint32_t* a, uint32_t addr) {
    asm volatile("ldmatrix.sync.aligned.m8n8.x4.shared.b16 {%0,%1,%2,%3}, [%4];"
                 : "=r"(a[0]), "=r"(a[1]), "=r"(a[2]), "=r"(a[3]) : "r"(addr));
}
__device__ __forceinline__ void mma16816(float* c, const uint32_t* a, const uint32_t* b) {
    asm volatile(
        "mma.sync.aligned.m16n8k16.row.col.f32.f16.f16.f32 "
        "{%0,%1,%2,%3}, {%4,%5,%6,%7}, {%8,%9}, {%0,%1,%2,%3};"
        : "+f"(c[0]), "+f"(c[1]), "+f"(c[2]), "+f"(c[3])
        : "r"(a[0]), "r"(a[1]), "r"(a[2]), "r"(a[3]), "r"(b[0]), "r"(b[1]));
}
__device__ __forceinline__ float gelu_exact(float x) {
    return 0.5f * x * (1.0f + erff(x * 0.70710678118654752f));
}

// ---------------- fused convert fp32 -> fp16 (single launch) ----------------
__global__ void convert_all(const float* __restrict__ qkv_w,
                            const float* __restrict__ out_w,
                            const float* __restrict__ fc1_w,
                            const float* __restrict__ fc2_w,
                            const float* __restrict__ head_w,
                            __half* __restrict__ w) {
    int stride = gridDim.x * blockDim.x;
    for (size_t i = blockIdx.x * blockDim.x + threadIdx.x; i < WTOT; i += stride) {
        float v;
        if (i < OOUT)       v = qkv_w[i - OQKV];
        else if (i < OFC1)  v = out_w[i - OOUT];
        else if (i < OFC2)  v = fc1_w[i - OFC1];
        else if (i < OHEAD) v = fc2_w[i - OFC2];
        else                v = head_w[i - OHEAD];
        w[i] = __float2half_rn(v);
    }
}

// ---------------- LayerNorm (fp32 in, fp16 out) ----------------
__global__ void ln_kernel(const float* __restrict__ x,
                          const float* __restrict__ w,
                          const float* __restrict__ b,
                          __half* __restrict__ y,
                          int rows, long long in_row_stride) {
    int row = blockIdx.x * (blockDim.x >> 5) + (threadIdx.x >> 5);
    if (row >= rows) return;
    int lane = threadIdx.x & 31;
    const float* xr = x + (long long)row * in_row_stride;
    float v[18];
    float s = 0.f;
#pragma unroll
    for (int i = 0; i < 18; i++) { v[i] = xr[lane + i * 32]; s += v[i]; }
#pragma unroll
    for (int o = 16; o; o >>= 1) s += __shfl_xor_sync(0xffffffffu, s, o);
    float mean = s * (1.0f / Dm);
    float s2 = 0.f;
#pragma unroll
    for (int i = 0; i < 18; i++) { float d = v[i] - mean; s2 += d * d; }
#pragma unroll
    for (int o = 16; o; o >>= 1) s2 += __shfl_xor_sync(0xffffffffu, s2, o);
    float inv = rsqrtf(s2 * (1.0f / Dm) + EPSV);
    __half* yr = y + (long long)row * Dm;
#pragma unroll
    for (int i = 0; i < 18; i++) {
        int d = lane + i * 32;
        yr[d] = __float2half_rn((v[i] - mean) * inv * w[d] + b[d]);
    }
}

// ---------------- Attention: one block per (batch, head), fp16 io ----------------
__global__ void attn_kernel(const __half* __restrict__ qkv,
                            const float* __restrict__ scale,
                            __half* __restrict__ o) {
    int b = blockIdx.x;
    int h = blockIdx.y;
    __shared__ float qs[Nt][DH];
    __shared__ float ks[Nt][DH];
    __shared__ float vs[Nt][DH];
    __shared__ float ss[Nt][32];
    int tid = threadIdx.x; // 128
    const __half* base = qkv + (long long)b * Nt * (3 * Dm) + h * DH;
    for (int idx = tid; idx < Nt * DH; idx += blockDim.x) {
        int n = idx / DH, d = idx % DH;
        const __half* p = base + (long long)n * (3 * Dm);
        qs[n][d] = __half2float(p[d]);
        ks[n][d] = __half2float(p[Dm + d]);
        vs[n][d] = __half2float(p[2 * Dm + d]);
    }
    __syncthreads();
    float sc = scale[h];
    for (int idx = tid; idx < Nt * Nt; idx += blockDim.x) {
        int i = idx / Nt, j = idx % Nt;
        if (i == j) { ss[i][j] = NEGV; continue; }
        float acc = 0.f;
#pragma unroll
        for (int d = 0; d < DH; d++) acc += qs[i][d] * ks[j][d];
        ss[i][j] = acc * sc;
    }
    __syncthreads();
    if (tid < Nt) {
        int i = tid;
        float mx = -3.4e38f;
#pragma unroll
        for (int j = 0; j < Nt; j++) mx = fmaxf(mx, ss[i][j]);
        float sum = 0.f;
#pragma unroll
        for (int j = 0; j < Nt; j++) { float e = expf(ss[i][j] - mx); ss[i][j] = e; sum += e; }
        float invs = 1.0f / sum;
#pragma unroll
        for (int j = 0; j < Nt; j++) ss[i][j] *= invs;
    }
    __syncthreads();
    for (int idx = tid; idx < Nt * DH; idx += blockDim.x) {
        int i = idx / DH, d = idx % DH;
        float acc = 0.f;
#pragma unroll
        for (int j = 0; j < Nt; j++) acc += ss[i][j] * vs[j][d];
        o[(long long)(b * Nt + i) * Dm + h * DH + d] = __float2half_rn(acc);
    }
}

// ---------------- HMMA GEMM: C[M,Nout] = A[M,K] * W[Nout,K]^T ----------------
// BM=128, BN=96, BK=64, 3-stage cp.async pipeline, ONE sync/iter, 8 warps (4m x 2n).
#define BM 128
#define BN 96
#define BK 64
#define STG 3
#define APAD 72   // halfs per smem row (64 data + 8 pad) -> 144B stride

template <bool NG>
__device__ __forceinline__ void load_tile(const __half* A, const __half* W,
                                          int Nout, int K, int m0, int n0, int k0,
                                          uint32_t sa, uint32_t sb, int tid) {
    // A: 128 rows x 8 chunks(16B) = 1024 chunks
#pragma unroll
    for (int i = 0; i < 4; i++) {
        int idx = tid + i * 256;
        int r = idx >> 3, ch = idx & 7;
        const __half* g = A + (size_t)(m0 + r) * K + k0 + ch * 8;
        cpasync16(sa + r * (APAD * 2) + ch * 16, g, 16);
    }
    // B: 96 rows x 8 chunks = 768 chunks
#pragma unroll
    for (int i = 0; i < 3; i++) {
        int idx = tid + i * 256;
        int r = idx >> 3, ch = idx & 7;
        int rr = n0 + r;
        uint32_t sz = 16;
        if (NG && rr >= Nout) { rr = 0; sz = 0; }
        const __half* g = W + (size_t)rr * K + k0 + ch * 8;
        cpasync16(sb + r * (APAD * 2) + ch * 16, g, sz);
    }
    asm volatile("cp.async.commit_group;" ::: "memory");
}

template <bool BIAS, bool RES, bool GELU, bool HALFOUT, bool NG>
__global__ __launch_bounds__(256) void hgemm(
    const __half* __restrict__ A, const __half* __restrict__ W,
    const float* __restrict__ bias, const float* __restrict__ resid,
    void* __restrict__ Cout, int M, int Nout, int K) {
    __shared__ __half As[STG][BM][APAD];
    __shared__ __half Bs[STG][BN][APAD];
    int tid = threadIdx.x, wid = tid >> 5, lane = tid & 31;
    int wm = wid >> 1, wn = wid & 1;
    int m0 = blockIdx.y * BM, n0 = blockIdx.x * BN;

    uint32_t sA[STG], sB[STG];
#pragma unroll
    for (int s = 0; s < STG; s++) {
        sA[s] = cvta_smem(&As[s][0][0]);
        sB[s] = cvta_smem(&Bs[s][0][0]);
    }

    float c[2][6][4];
#pragma unroll
    for (int mi = 0; mi < 2; mi++)
#pragma unroll
        for (int ni = 0; ni < 6; ni++)
#pragma unroll
            for (int j = 0; j < 4; j++) c[mi][ni][j] = 0.f;

    const int T = K / BK;
    load_tile<NG>(A, W, Nout, K, m0, n0, 0,  sA[0], sB[0], tid);
    load_tile<NG>(A, W, Nout, K, m0, n0, BK, sA[1], sB[1], tid);

    // ldmatrix address components
    uint32_t aRow = (uint32_t)(wm * 32 + (lane & 15));
    uint32_t aCol8 = (uint32_t)((lane >> 4) * 8);
    int t4 = lane >> 3, r8 = lane & 7;
    uint32_t bBase = (uint32_t)((wn * 48 + (t4 >> 1) * 8 + r8) * APAD + (t4 & 1) * 8);

    for (int t = 0; t < T; t++) {
        asm volatile("cp.async.wait_group 1;" ::: "memory");
        __syncthreads();
        if (t + 2 < T) {
            load_tile<NG>(A, W, Nout, K, m0, n0, (t + 2) * BK,
                          sA[(t + 2) % STG], sB[(t + 2) % STG], tid);
        } else {
            asm volatile("cp.async.commit_group;" ::: "memory");
        }
        int s = t % STG;
#pragma unroll
        for (int ks = 0; ks < 4; ks++) {
            uint32_t a[2][4], b[6][2];
#pragma unroll
            for (int mi = 0; mi < 2; mi++)
                ldm4(a[mi], sA[s] + ((aRow + mi * 16) * APAD + ks * 16 + aCol8) * 2);
#pragma unroll
            for (int nb = 0; nb < 3; nb++) {
                uint32_t bb[4];
                ldm4(bb, sB[s] + (bBase + nb * 16 * APAD + ks * 16) * 2);
                b[nb * 2 + 0][0] = bb[0]; b[nb * 2 + 0][1] = bb[1];
                b[nb * 2 + 1][0] = bb[2]; b[nb * 2 + 1][1] = bb[3];
            }
#pragma unroll
            for (int mi = 0; mi < 2; mi++)
#pragma unroll
                for (int ni = 0; ni < 6; ni++)
                    mma16816(c[mi][ni], a[mi], b[ni]);
        }
    }

    // epilogue (no barrier needed: last buffers not rewritten)
    int rbase = m0 + wm * 32 + (lane >> 2);
    int cbase = n0 + wn * 48 + (lane & 3) * 2;
#pragma unroll
    for (int mi = 0; mi < 2; mi++) {
#pragma unroll
        for (int half = 0; half < 2; half++) {
            size_t row = (size_t)(rbase + mi * 16 + half * 8);
#pragma unroll
            for (int ni = 0; ni < 6; ni++) {
                int col = cbase + ni * 8;
                if (!NG || col + 1 < Nout) {
                    float v0 = c[mi][ni][half * 2 + 0];
                    float v1 = c[mi][ni][half * 2 + 1];
                    if (BIAS) { v0 += bias[col]; v1 += bias[col + 1]; }
                    if (GELU) { v0 = gelu_exact(v0); v1 = gelu_exact(v1); }
                    if (RES) {
                        v0 += resid[row * Nout + col];
                        v1 += resid[row * Nout + col + 1];
                    }
                    if (HALFOUT) {
                        *(__half2*)((__half*)Cout + row * Nout + col) =
                            __floats2half2_rn(v0, v1);
                    } else {
                        *(float2*)((float*)Cout + row * Nout + col) =
                            make_float2(v0, v1);
                    }
                }
            }
        }
    }
}

// ---------------- Host launcher ----------------
extern "C" void kernel_launch(void* const* d_in, const int* in_sizes, int n_in,
                              void* d_out, int out_size) {
    const float* x      = (const float*)d_in[0];
    const float* qkv_w  = (const float*)d_in[1];
    const float* scale  = (const float*)d_in[2];
    const float* out_w  = (const float*)d_in[3];
    const float* out_b  = (const float*)d_in[4];
    const float* ln1_w  = (const float*)d_in[5];
    const float* ln1_b  = (const float*)d_in[6];
    const float* ln2_w  = (const float*)d_in[7];
    const float* ln2_b  = (const float*)d_in[8];
    const float* fc1_w  = (const float*)d_in[9];
    const float* fc1_b  = (const float*)d_in[10];
    const float* fc2_w  = (const float*)d_in[11];
    const float* fc2_b  = (const float*)d_in[12];
    const float* norm_w = (const float*)d_in[13];
    const float* norm_b = (const float*)d_in[14];
    const float* head_w = (const float*)d_in[15];
    const float* head_b = (const float*)d_in[16];
    float* out = (float*)d_out;

    float  *h;
    __half *y, *qkv, *o, *m, *cls, *w16;
    cudaGetSymbolAddress((void**)&h,   g_h);
    cudaGetSymbolAddress((void**)&y,   g_y);
    cudaGetSymbolAddress((void**)&qkv, g_qkv);
    cudaGetSymbolAddress((void**)&o,   g_o);
    cudaGetSymbolAddress((void**)&m,   g_m);
    cudaGetSymbolAddress((void**)&cls, g_cls);
    cudaGetSymbolAddress((void**)&w16, g_w16);

    cudaMemcpyAsync(h, x, sizeof(float) * (size_t)RROWS * Dm, cudaMemcpyDeviceToDevice);

    // single fused weight conversion (launch #1)
    convert_all<<<4096, 256>>>(qkv_w, out_w, fc1_w, fc2_w, head_w, w16);

    dim3 gQKV(3 * Dm / BN, RROWS / BM);   // (18, 248)
    dim3 gPROJ(Dm / BN, RROWS / BM);      // (6, 248)
    dim3 gFC1(FF / BN, RROWS / BM);       // (24, 248)
    dim3 gATT(Bz, Hh);
    int lnBlocks = RROWS / 8;

    for (int l = 0; l < Ll; l++) {
        const __half* qw = w16 + OQKV + (size_t)l * 3 * Dm * Dm;
        const __half* ow = w16 + OOUT + (size_t)l * Dm * Dm;
        const __half* w1 = w16 + OFC1 + (size_t)l * FF * Dm;
        const __half* w2 = w16 + OFC2 + (size_t)l * Dm * FF;

        ln_kernel<<<lnBlocks, 256>>>(h, ln1_w + l * Dm, ln1_b + l * Dm, y, RROWS, Dm);
        hgemm<false, false, false, true, false><<<gQKV, 256>>>(
            y, qw, nullptr, nullptr, qkv, RROWS, 3 * Dm, Dm);
        attn_kernel<<<gATT, 128>>>(qkv, scale + l * Hh, o);
        hgemm<true, true, false, false, false><<<gPROJ, 256>>>(
            o, ow, out_b + l * Dm, h, h, RROWS, Dm, Dm);
        ln_kernel<<<lnBlocks, 256>>>(h, ln2_w + l * Dm, ln2_b + l * Dm, y, RROWS, Dm);
        hgemm<true, false, true, true, false><<<gFC1, 256>>>(
            y, w1, fc1_b + l * FF, nullptr, m, RROWS, FF, Dm);
        hgemm<true, true, false, false, false><<<gPROJ, 256>>>(
            m, w2, fc2_b + l * Dm, h, h, RROWS, Dm, FF);
    }

    // final LN on cls tokens, then classifier head
    ln_kernel<<<Bz / 8, 256>>>(h, norm_w, norm_b, cls, Bz, (long long)Nt * Dm);
    dim3 gHEAD((NC + BN - 1) / BN, Bz / BM); // (11, 8)
    hgemm<true, false, false, false, true><<<gHEAD, 256>>>(
        cls, w16 + OHEAD, head_b, nullptr, out, Bz, NC, Dm);
}

// round 7
// speedup vs baseline: 5.1793x; 1.0273x over previous
#include <cuda_runtime.h>
#include <cuda_fp16.h>
#include <math.h>
#include <stdint.h>

// ---------------- Problem constants ----------------
#define Bz   1024
#define Nt   31
#define Dm   576
#define Hh   16
#define Ll   12
#define DH   36
#define FF   2304
#define NC   1000
#define EPSV 1e-5f
#define NEGV -987654321.0f
#define RROWS (Bz * Nt) // 31744

// ---------------- Scratch ----------------
__device__ float  g_h  [(size_t)RROWS * Dm];
__device__ __half g_y  [(size_t)RROWS * Dm];
__device__ __half g_qkv[(size_t)RROWS * 3 * Dm];
__device__ __half g_o  [(size_t)RROWS * Dm];
__device__ __half g_m  [(size_t)RROWS * FF];
__device__ __half g_cls[(size_t)Bz * Dm];

// fp16 weight arena
#define OQKV  0
#define OOUT  11943936
#define OFC1  15925248
#define OFC2  31850496
#define OHEAD 47775744
#define WTOT  48351744
__device__ __half g_w16[WTOT];

// ---------------- helpers ----------------
__device__ __forceinline__ uint32_t cvta_smem(const void* p) {
    uint32_t a;
    asm("{ .reg .u64 t; cvta.to.shared.u64 t, %1; cvt.u32.u64 %0, t; }" : "=r"(a) : "l"(p));
    return a;
}
__device__ __forceinline__ void cpasync16(uint32_t dst, const void* src, uint32_t srcsize) {
    asm volatile("cp.async.cg.shared.global [%0], [%1], 16, %2;"
                 :: "r"(dst), "l"(src), "r"(srcsize));
}
__device__ __forceinline__ void ldm4(uint32_t* a, uint32_t addr) {
    asm volatile("ldmatrix.sync.aligned.m8n8.x4.shared.b16 {%0,%1,%2,%3}, [%4];"
                 : "=r"(a[0]), "=r"(a[1]), "=r"(a[2]), "=r"(a[3]) : "r"(addr));
}
__device__ __forceinline__ void mma16816(float* c, const uint32_t* a, const uint32_t* b) {
    asm volatile(
        "mma.sync.aligned.m16n8k16.row.col.f32.f16.f16.f32 "
        "{%0,%1,%2,%3}, {%4,%5,%6,%7}, {%8,%9}, {%0,%1,%2,%3};"
        : "+f"(c[0]), "+f"(c[1]), "+f"(c[2]), "+f"(c[3])
        : "r"(a[0]), "r"(a[1]), "r"(a[2]), "r"(a[3]), "r"(b[0]), "r"(b[1]));
}
__device__ __forceinline__ float gelu_exact(float x) {
    return 0.5f * x * (1.0f + erff(x * 0.70710678118654752f));
}

// ---------------- fused convert fp32 -> fp16 (single launch) ----------------
__global__ void convert_all(const float* __restrict__ qkv_w,
                            const float* __restrict__ out_w,
                            const float* __restrict__ fc1_w,
                            const float* __restrict__ fc2_w,
                            const float* __restrict__ head_w,
                            __half* __restrict__ w) {
    int stride = gridDim.x * blockDim.x;
    for (size_t i = blockIdx.x * blockDim.x + threadIdx.x; i < WTOT; i += stride) {
        float v;
        if (i < OOUT)       v = qkv_w[i - OQKV];
        else if (i < OFC1)  v = out_w[i - OOUT];
        else if (i < OFC2)  v = fc1_w[i - OFC1];
        else if (i < OHEAD) v = fc2_w[i - OFC2];
        else                v = head_w[i - OHEAD];
        w[i] = __float2half_rn(v);
    }
}

// ---------------- LayerNorm (fp32 in, fp16 out) ----------------
__global__ void ln_kernel(const float* __restrict__ x,
                          const float* __restrict__ w,
                          const float* __restrict__ b,
                          __half* __restrict__ y,
                          int rows, long long in_row_stride) {
    int row = blockIdx.x * (blockDim.x >> 5) + (threadIdx.x >> 5);
    if (row >= rows) return;
    int lane = threadIdx.x & 31;
    const float* xr = x + (long long)row * in_row_stride;
    float v[18];
    float s = 0.f;
#pragma unroll
    for (int i = 0; i < 18; i++) { v[i] = xr[lane + i * 32]; s += v[i]; }
#pragma unroll
    for (int o = 16; o; o >>= 1) s += __shfl_xor_sync(0xffffffffu, s, o);
    float mean = s * (1.0f / Dm);
    float s2 = 0.f;
#pragma unroll
    for (int i = 0; i < 18; i++) { float d = v[i] - mean; s2 += d * d; }
#pragma unroll
    for (int o = 16; o; o >>= 1) s2 += __shfl_xor_sync(0xffffffffu, s2, o);
    float inv = rsqrtf(s2 * (1.0f / Dm) + EPSV);
    __half* yr = y + (long long)row * Dm;
#pragma unroll
    for (int i = 0; i < 18; i++) {
        int d = lane + i * 32;
        yr[d] = __float2half_rn((v[i] - mean) * inv * w[d] + b[d]);
    }
}

// ---------------- Attention: one block per (batch, head), conflict-free smem ----
#define QP 37   // row stride for q/k/v tiles: (37*j+d)%32=(5j+d)%32, conflict-free
#define SP 33   // row stride for scores: (33*i+j)%32=(i+j)%32, conflict-free

__global__ void attn_kernel(const __half* __restrict__ qkv,
                            const float* __restrict__ scale,
                            __half* __restrict__ o) {
    int b = blockIdx.x;
    int h = blockIdx.y;
    __shared__ float qs[Nt][QP];
    __shared__ float ks[Nt][QP];
    __shared__ float vs[Nt][QP];
    __shared__ float ss[Nt][SP];
    int tid = threadIdx.x; // 128
    // vectorized half2 loads: 31 rows x 18 half2 per tensor
    const __half2* base2 = (const __half2*)(qkv + (long long)b * Nt * (3 * Dm) + h * DH);
    for (int idx = tid; idx < Nt * (DH / 2); idx += blockDim.x) {
        int n = idx / (DH / 2), dp = idx % (DH / 2);
        const __half2* p = base2 + (long long)n * (3 * Dm / 2) + dp;
        float2 qf = __half22float2(p[0]);
        float2 kf = __half22float2(p[Dm / 2]);
        float2 vf = __half22float2(p[Dm]);
        qs[n][2 * dp] = qf.x; qs[n][2 * dp + 1] = qf.y;
        ks[n][2 * dp] = kf.x; ks[n][2 * dp + 1] = kf.y;
        vs[n][2 * dp] = vf.x; vs[n][2 * dp + 1] = vf.y;
    }
    __syncthreads();
    float sc = scale[h];
    for (int idx = tid; idx < Nt * Nt; idx += blockDim.x) {
        int i = idx / Nt, j = idx % Nt;
        if (i == j) { ss[i][j] = NEGV; continue; }
        float acc = 0.f;
#pragma unroll
        for (int d = 0; d < DH; d++) acc += qs[i][d] * ks[j][d];
        ss[i][j] = acc * sc;
    }
    __syncthreads();
    if (tid < Nt) {
        int i = tid;
        float mx = -3.4e38f;
#pragma unroll
        for (int j = 0; j < Nt; j++) mx = fmaxf(mx, ss[i][j]);
        float sum = 0.f;
#pragma unroll
        for (int j = 0; j < Nt; j++) { float e = expf(ss[i][j] - mx); ss[i][j] = e; sum += e; }
        float invs = 1.0f / sum;
#pragma unroll
        for (int j = 0; j < Nt; j++) ss[i][j] *= invs;
    }
    __syncthreads();
    for (int idx = tid; idx < Nt * (DH / 2); idx += blockDim.x) {
        int i = idx / (DH / 2), dp = idx % (DH / 2);
        int d = dp * 2;
        float a0 = 0.f, a1 = 0.f;
#pragma unroll
        for (int j = 0; j < Nt; j++) {
            float w = ss[i][j];
            a0 += w * vs[j][d];
            a1 += w * vs[j][d + 1];
        }
        *(__half2*)(o + (long long)(b * Nt + i) * Dm + h * DH + d) =
            __floats2half2_rn(a0, a1);
    }
}

// ---------------- HMMA GEMM: C[M,Nout] = A[M,K] * W[Nout,K]^T ----------------
// BM=128, BN=96, BK=64, 3-stage cp.async pipeline, ONE sync/iter, 8 warps (4m x 2n).
#define BM 128
#define BN 96
#define BK 64
#define STG 3
#define APAD 72   // halfs per smem row (64 data + 8 pad) -> 144B stride

template <bool NG>
__device__ __forceinline__ void load_tile(const __half* A, const __half* W,
                                          int Nout, int K, int m0, int n0, int k0,
                                          uint32_t sa, uint32_t sb, int tid) {
#pragma unroll
    for (int i = 0; i < 4; i++) {
        int idx = tid + i * 256;
        int r = idx >> 3, ch = idx & 7;
        const __half* g = A + (size_t)(m0 + r) * K + k0 + ch * 8;
        cpasync16(sa + r * (APAD * 2) + ch * 16, g, 16);
    }
#pragma unroll
    for (int i = 0; i < 3; i++) {
        int idx = tid + i * 256;
        int r = idx >> 3, ch = idx & 7;
        int rr = n0 + r;
        uint32_t sz = 16;
        if (NG && rr >= Nout) { rr = 0; sz = 0; }
        const __half* g = W + (size_t)rr * K + k0 + ch * 8;
        cpasync16(sb + r * (APAD * 2) + ch * 16, g, sz);
    }
    asm volatile("cp.async.commit_group;" ::: "memory");
}

template <bool BIAS, bool RES, bool GELU, bool HALFOUT, bool NG>
__global__ __launch_bounds__(256) void hgemm(
    const __half* __restrict__ A, const __half* __restrict__ W,
    const float* __restrict__ bias, const float* __restrict__ resid,
    void* __restrict__ Cout, int M, int Nout, int K) {
    __shared__ __half As[STG][BM][APAD];
    __shared__ __half Bs[STG][BN][APAD];
    int tid = threadIdx.x, wid = tid >> 5, lane = tid & 31;
    int wm = wid >> 1, wn = wid & 1;
    int m0 = blockIdx.y * BM, n0 = blockIdx.x * BN;

    uint32_t sA[STG], sB[STG];
#pragma unroll
    for (int s = 0; s < STG; s++) {
        sA[s] = cvta_smem(&As[s][0][0]);
        sB[s] = cvta_smem(&Bs[s][0][0]);
    }

    float c[2][6][4];
#pragma unroll
    for (int mi = 0; mi < 2; mi++)
#pragma unroll
        for (int ni = 0; ni < 6; ni++)
#pragma unroll
            for (int j = 0; j < 4; j++) c[mi][ni][j] = 0.f;

    const int T = K / BK;
    load_tile<NG>(A, W, Nout, K, m0, n0, 0,  sA[0], sB[0], tid);
    load_tile<NG>(A, W, Nout, K, m0, n0, BK, sA[1], sB[1], tid);

    uint32_t aRow = (uint32_t)(wm * 32 + (lane & 15));
    uint32_t aCol8 = (uint32_t)((lane >> 4) * 8);
    int t4 = lane >> 3, r8 = lane & 7;
    uint32_t bBase = (uint32_t)((wn * 48 + (t4 >> 1) * 8 + r8) * APAD + (t4 & 1) * 8);

    for (int t = 0; t < T; t++) {
        asm volatile("cp.async.wait_group 1;" ::: "memory");
        __syncthreads();
        if (t + 2 < T) {
            load_tile<NG>(A, W, Nout, K, m0, n0, (t + 2) * BK,
                          sA[(t + 2) % STG], sB[(t + 2) % STG], tid);
        } else {
            asm volatile("cp.async.commit_group;" ::: "memory");
        }
        int s = t % STG;
#pragma unroll
        for (int ks = 0; ks < 4; ks++) {
            uint32_t a[2][4], b[6][2];
#pragma unroll
            for (int mi = 0; mi < 2; mi++)
                ldm4(a[mi], sA[s] + ((aRow + mi * 16) * APAD + ks * 16 + aCol8) * 2);
#pragma unroll
            for (int nb = 0; nb < 3; nb++) {
                uint32_t bb[4];
                ldm4(bb, sB[s] + (bBase + nb * 16 * APAD + ks * 16) * 2);
                b[nb * 2 + 0][0] = bb[0]; b[nb * 2 + 0][1] = bb[1];
                b[nb * 2 + 1][0] = bb[2]; b[nb * 2 + 1][1] = bb[3];
            }
#pragma unroll
            for (int mi = 0; mi < 2; mi++)
#pragma unroll
                for (int ni = 0; ni < 6; ni++)
                    mma16816(c[mi][ni], a[mi], b[ni]);
        }
    }

    // epilogue
    int rbase = m0 + wm * 32 + (lane >> 2);
    int cbase = n0 + wn * 48 + (lane & 3) * 2;
#pragma unroll
    for (int mi = 0; mi < 2; mi++) {
#pragma unroll
        for (int half = 0; half < 2; half++) {
            size_t row = (size_t)(rbase + mi * 16 + half * 8);
#pragma unroll
            for (int ni = 0; ni < 6; ni++) {
                int col = cbase + ni * 8;
                if (!NG || col + 1 < Nout) {
                    float v0 = c[mi][ni][half * 2 + 0];
                    float v1 = c[mi][ni][half * 2 + 1];
                    if (BIAS) { v0 += bias[col]; v1 += bias[col + 1]; }
                    if (GELU) { v0 = gelu_exact(v0); v1 = gelu_exact(v1); }
                    if (RES) {
                        v0 += resid[row * Nout + col];
                        v1 += resid[row * Nout + col + 1];
                    }
                    if (HALFOUT) {
                        *(__half2*)((__half*)Cout + row * Nout + col) =
                            __floats2half2_rn(v0, v1);
                    } else {
                        *(float2*)((float*)Cout + row * Nout + col) =
                            make_float2(v0, v1);
                    }
                }
            }
        }
    }
}

// ---------------- Host launcher ----------------
extern "C" void kernel_launch(void* const* d_in, const int* in_sizes, int n_in,
                              void* d_out, int out_size) {
    const float* x      = (const float*)d_in[0];
    const float* qkv_w  = (const float*)d_in[1];
    const float* scale  = (const float*)d_in[2];
    const float* out_w  = (const float*)d_in[3];
    const float* out_b  = (const float*)d_in[4];
    const float* ln1_w  = (const float*)d_in[5];
    const float* ln1_b  = (const float*)d_in[6];
    const float* ln2_w  = (const float*)d_in[7];
    const float* ln2_b  = (const float*)d_in[8];
    const float* fc1_w  = (const float*)d_in[9];
    const float* fc1_b  = (const float*)d_in[10];
    const float* fc2_w  = (const float*)d_in[11];
    const float* fc2_b  = (const float*)d_in[12];
    const float* norm_w = (const float*)d_in[13];
    const float* norm_b = (const float*)d_in[14];
    const float* head_w = (const float*)d_in[15];
    const float* head_b = (const float*)d_in[16];
    float* out = (float*)d_out;

    float  *h;
    __half *y, *qkv, *o, *m, *cls, *w16;
    cudaGetSymbolAddress((void**)&h,   g_h);
    cudaGetSymbolAddress((void**)&y,   g_y);
    cudaGetSymbolAddress((void**)&qkv, g_qkv);
    cudaGetSymbolAddress((void**)&o,   g_o);
    cudaGetSymbolAddress((void**)&m,   g_m);
    cudaGetSymbolAddress((void**)&cls, g_cls);
    cudaGetSymbolAddress((void**)&w16, g_w16);

    cudaMemcpyAsync(h, x, sizeof(float) * (size_t)RROWS * Dm, cudaMemcpyDeviceToDevice);

    convert_all<<<4096, 256>>>(qkv_w, out_w, fc1_w, fc2_w, head_w, w16);

    dim3 gQKV(3 * Dm / BN, RROWS / BM);   // (18, 248)
    dim3 gPROJ(Dm / BN, RROWS / BM);      // (6, 248)
    dim3 gFC1(FF / BN, RROWS / BM);       // (24, 248)
    dim3 gATT(Bz, Hh);
    int lnBlocks = RROWS / 8;

    for (int l = 0; l < Ll; l++) {
        const __half* qw = w16 + OQKV + (size_t)l * 3 * Dm * Dm;
        const __half* ow = w16 + OOUT + (size_t)l * Dm * Dm;
        const __half* w1 = w16 + OFC1 + (size_t)l * FF * Dm;
        const __half* w2 = w16 + OFC2 + (size_t)l * Dm * FF;

        ln_kernel<<<lnBlocks, 256>>>(h, ln1_w + l * Dm, ln1_b + l * Dm, y, RROWS, Dm);
        hgemm<false, false, false, true, false><<<gQKV, 256>>>(
            y, qw, nullptr, nullptr, qkv, RROWS, 3 * Dm, Dm);
        attn_kernel<<<gATT, 128>>>(qkv, scale + l * Hh, o);
        hgemm<true, true, false, false, false><<<gPROJ, 256>>>(
            o, ow, out_b + l * Dm, h, h, RROWS, Dm, Dm);
        ln_kernel<<<lnBlocks, 256>>>(h, ln2_w + l * Dm, ln2_b + l * Dm, y, RROWS, Dm);
        hgemm<true, false, true, true, false><<<gFC1, 256>>>(
            y, w1, fc1_b + l * FF, nullptr, m, RROWS, FF, Dm);
        hgemm<true, true, false, false, false><<<gPROJ, 256>>>(
            m, w2, fc2_b + l * Dm, h, h, RROWS, Dm, FF);
    }

    ln_kernel<<<Bz / 8, 256>>>(h, norm_w, norm_b, cls, Bz, (long long)Nt * Dm);
    dim3 gHEAD((NC + BN - 1) / BN, Bz / BM); // (11, 8)
    hgemm<true, false, false, false, true><<<gHEAD, 256>>>(
        cls, w16 + OHEAD, head_b, nullptr, out, Bz, NC, Dm);
}

// round 9
// speedup vs baseline: 5.6152x; 1.0842x over previous
#include <cuda_runtime.h>
#include <cuda_fp16.h>
#include <math.h>
#include <stdint.h>

// ---------------- Problem constants ----------------
#define Bz   1024
#define Nt   31
#define Dm   576
#define Hh   16
#define Ll   12
#define DH   36
#define FF   2304
#define NC   1000
#define EPSV 1e-5f
#define NEGV -987654321.0f
#define RROWS (Bz * Nt) // 31744

// ---------------- Scratch ----------------
__device__ float  g_h  [(size_t)RROWS * Dm];
__device__ __half g_y  [(size_t)RROWS * Dm];
__device__ __half g_qkv[(size_t)RROWS * 3 * Dm];
__device__ __half g_o  [(size_t)RROWS * Dm];
__device__ __half g_m  [(size_t)RROWS * FF];
__device__ __half g_cls[(size_t)Bz * Dm];

// fp16 weight arena
#define OQKV  0
#define OOUT  11943936
#define OFC1  15925248
#define OFC2  31850496
#define OHEAD 47775744
#define WTOT  48351744
__device__ __half g_w16[WTOT];

// ---------------- helpers ----------------
__device__ __forceinline__ uint32_t cvta_smem(const void* p) {
    uint32_t a;
    asm("{ .reg .u64 t; cvta.to.shared.u64 t, %1; cvt.u32.u64 %0, t; }" : "=r"(a) : "l"(p));
    return a;
}
__device__ __forceinline__ void cpasync16(uint32_t dst, const void* src, uint32_t srcsize) {
    asm volatile("cp.async.cg.shared.global [%0], [%1], 16, %2;"
                 :: "r"(dst), "l"(src), "r"(srcsize));
}
__device__ __forceinline__ void ldm4(uint32_t* a, uint32_t addr) {
    asm volatile("ldmatrix.sync.aligned.m8n8.x4.shared.b16 {%0,%1,%2,%3}, [%4];"
                 : "=r"(a[0]), "=r"(a[1]), "=r"(a[2]), "=r"(a[3]) : "r"(addr));
}
__device__ __forceinline__ void mma16816(float* c, const uint32_t* a, const uint32_t* b) {
    asm volatile(
        "mma.sync.aligned.m16n8k16.row.col.f32.f16.f16.f32 "
        "{%0,%1,%2,%3}, {%4,%5,%6,%7}, {%8,%9}, {%0,%1,%2,%3};"
        : "+f"(c[0]), "+f"(c[1]), "+f"(c[2]), "+f"(c[3])
        : "r"(a[0]), "r"(a[1]), "r"(a[2]), "r"(a[3]), "r"(b[0]), "r"(b[1]));
}
__device__ __forceinline__ float gelu_exact(float x) {
    return 0.5f * x * (1.0f + erff(x * 0.70710678118654752f));
}

// ---------------- fused convert fp32 -> fp16 (single launch) ----------------
__global__ void convert_all(const float* __restrict__ qkv_w,
                            const float* __restrict__ out_w,
                            const float* __restrict__ fc1_w,
                            const float* __restrict__ fc2_w,
                            const float* __restrict__ head_w,
                            __half* __restrict__ w) {
    int stride = gridDim.x * blockDim.x;
    for (size_t i = blockIdx.x * blockDim.x + threadIdx.x; i < WTOT; i += stride) {
        float v;
        if (i < OOUT)       v = qkv_w[i - OQKV];
        else if (i < OFC1)  v = out_w[i - OOUT];
        else if (i < OFC2)  v = fc1_w[i - OFC1];
        else if (i < OHEAD) v = fc2_w[i - OFC2];
        else                v = head_w[i - OHEAD];
        w[i] = __float2half_rn(v);
    }
}

// ---------------- LayerNorm (fp32 in, fp16 out) ----------------
__global__ void ln_kernel(const float* __restrict__ x,
                          const float* __restrict__ w,
                          const float* __restrict__ b,
                          __half* __restrict__ y,
                          int rows, long long in_row_stride) {
    int row = blockIdx.x * (blockDim.x >> 5) + (threadIdx.x >> 5);
    if (row >= rows) return;
    int lane = threadIdx.x & 31;
    const float* xr = x + (long long)row * in_row_stride;
    float v[18];
    float s = 0.f;
#pragma unroll
    for (int i = 0; i < 18; i++) { v[i] = xr[lane + i * 32]; s += v[i]; }
#pragma unroll
    for (int o = 16; o; o >>= 1) s += __shfl_xor_sync(0xffffffffu, s, o);
    float mean = s * (1.0f / Dm);
    float s2 = 0.f;
#pragma unroll
    for (int i = 0; i < 18; i++) { float d = v[i] - mean; s2 += d * d; }
#pragma unroll
    for (int o = 16; o; o >>= 1) s2 += __shfl_xor_sync(0xffffffffu, s2, o);
    float inv = rsqrtf(s2 * (1.0f / Dm) + EPSV);
    __half* yr = y + (long long)row * Dm;
#pragma unroll
    for (int i = 0; i < 18; i++) {
        int d = lane + i * 32;
        yr[d] = __float2half_rn((v[i] - mean) * inv * w[d] + b[d]);
    }
}

// ---------------- Attention: register-tiled, one block per (batch, head) ----------
#define QP 37   // row stride for q/k/v tiles (floats): conflict-free
#define SP 33   // row stride for scores

__global__ void attn_kernel(const __half* __restrict__ qkv,
                            const float* __restrict__ scale,
                            __half* __restrict__ o) {
    int b = blockIdx.x;
    int h = blockIdx.y;
    __shared__ float qs[32][QP];
    __shared__ float ks[32][QP];
    __shared__ float vs[32][QP];
    __shared__ float ss[32][SP];
    int tid = threadIdx.x; // 128

    // load q/k/v (rows >= Nt zero-filled)
    const __half2* base2 = (const __half2*)(qkv + (long long)b * Nt * (3 * Dm) + h * DH);
    for (int idx = tid; idx < 32 * (DH / 2); idx += 128) {
        int n = idx / (DH / 2), dp = idx % (DH / 2);
        float2 qf = make_float2(0.f, 0.f), kf = qf, vf = qf;
        if (n < Nt) {
            const __half2* p = base2 + (long long)n * (3 * Dm / 2) + dp;
            qf = __half22float2(p[0]);
            kf = __half22float2(p[Dm / 2]);
            vf = __half22float2(p[Dm]);
        }
        qs[n][2 * dp] = qf.x; qs[n][2 * dp + 1] = qf.y;
        ks[n][2 * dp] = kf.x; ks[n][2 * dp + 1] = kf.y;
        vs[n][2 * dp] = vf.x; vs[n][2 * dp + 1] = vf.y;
    }
    __syncthreads();

    float sc = scale[h];

    // ---- QK: 16(i) x 8(j) thread grid; per-thread 2 rows x 4 cols ----
    {
        int ti = tid >> 3, tj = tid & 7;
        int i0 = ti, i1 = ti + 16, j0 = tj * 4;
        float acc[2][4];
#pragma unroll
        for (int r = 0; r < 2; r++)
#pragma unroll
            for (int jj = 0; jj < 4; jj++) acc[r][jj] = 0.f;
#pragma unroll
        for (int d = 0; d < DH; d++) {
            float q0 = qs[i0][d], q1 = qs[i1][d];
#pragma unroll
            for (int jj = 0; jj < 4; jj++) {
                float kv = ks[j0 + jj][d];
                acc[0][jj] = fmaf(q0, kv, acc[0][jj]);
                acc[1][jj] = fmaf(q1, kv, acc[1][jj]);
            }
        }
#pragma unroll
        for (int r = 0; r < 2; r++) {
            int i = (r == 0) ? i0 : i1;
#pragma unroll
            for (int jj = 0; jj < 4; jj++) {
                int j = j0 + jj;
                ss[i][j] = (i == j) ? NEGV : acc[r][jj] * sc;
            }
        }
    }
    __syncthreads();

    // ---- softmax: ALL 128 threads (32 rows x 4 lanes); row 31 is padding, harmless
    {
        int i = tid >> 2, q = tid & 3;
        int jb = q * 8;
        float mx = -3.4e38f;
#pragma unroll
        for (int jj = 0; jj < 8; jj++) {
            int j = jb + jj;
            if (j < Nt) mx = fmaxf(mx, ss[i][j]);
        }
        mx = fmaxf(mx, __shfl_xor_sync(0xffffffffu, mx, 1));
        mx = fmaxf(mx, __shfl_xor_sync(0xffffffffu, mx, 2));
        float e[8];
        float sum = 0.f;
#pragma unroll
        for (int jj = 0; jj < 8; jj++) {
            int j = jb + jj;
            if (j < Nt) { e[jj] = expf(ss[i][j] - mx); sum += e[jj]; }
            else e[jj] = 0.f;
        }
        sum += __shfl_xor_sync(0xffffffffu, sum, 1);
        sum += __shfl_xor_sync(0xffffffffu, sum, 2);
        float inv = 1.0f / sum;
        __syncthreads();   // all ss reads done before writes below
#pragma unroll
        for (int jj = 0; jj < 8; jj++) {
            int j = jb + jj;
            ss[i][j] = e[jj] * inv;  // j==31 -> 0
        }
    }
    __syncthreads();

    // ---- AV: 8(i) x 16(d) thread grid; per-thread 4 rows x 2 d (x2 chunks) ----
    {
        int ti = tid >> 4, tdp = tid & 15;
#pragma unroll
        for (int c = 0; c < 2; c++) {
            int d = 2 * (tdp + 16 * c);
            if (d < DH) {
                float a[4][2];
#pragma unroll
                for (int r = 0; r < 4; r++) { a[r][0] = 0.f; a[r][1] = 0.f; }
#pragma unroll
                for (int j = 0; j < 32; j++) {
                    float v0 = vs[j][d], v1 = vs[j][d + 1];
#pragma unroll
                    for (int r = 0; r < 4; r++) {
                        float w = ss[ti + 8 * r][j];
                        a[r][0] = fmaf(w, v0, a[r][0]);
                        a[r][1] = fmaf(w, v1, a[r][1]);
                    }
                }
#pragma unroll
                for (int r = 0; r < 4; r++) {
                    int i = ti + 8 * r;
                    if (i < Nt) {
                        *(__half2*)(o + (long long)(b * Nt + i) * Dm + h * DH + d) =
                            __floats2half2_rn(a[r][0], a[r][1]);
                    }
                }
            }
        }
    }
}

// ---------------- HMMA GEMM: C[M,Nout] = A[M,K] * W[Nout,K]^T ----------------
#define BM 128
#define BN 96
#define BK 64
#define STG 3
#define APAD 72

template <bool NG>
__device__ __forceinline__ void load_tile(const __half* A, const __half* W,
                                          int Nout, int K, int m0, int n0, int k0,
                                          uint32_t sa, uint32_t sb, int tid) {
#pragma unroll
    for (int i = 0; i < 4; i++) {
        int idx = tid + i * 256;
        int r = idx >> 3, ch = idx & 7;
        const __half* g = A + (size_t)(m0 + r) * K + k0 + ch * 8;
        cpasync16(sa + r * (APAD * 2) + ch * 16, g, 16);
    }
#pragma unroll
    for (int i = 0; i < 3; i++) {
        int idx = tid + i * 256;
        int r = idx >> 3, ch = idx & 7;
        int rr = n0 + r;
        uint32_t sz = 16;
        if (NG && rr >= Nout) { rr = 0; sz = 0; }
        const __half* g = W + (size_t)rr * K + k0 + ch * 8;
        cpasync16(sb + r * (APAD * 2) + ch * 16, g, sz);
    }
    asm volatile("cp.async.commit_group;" ::: "memory");
}

template <bool BIAS, bool RES, bool GELU, bool HALFOUT, bool NG>
__global__ __launch_bounds__(256) void hgemm(
    const __half* __restrict__ A, const __half* __restrict__ W,
    const float* __restrict__ bias, const float* __restrict__ resid,
    void* __restrict__ Cout, int M, int Nout, int K) {
    __shared__ __half As[STG][BM][APAD];
    __shared__ __half Bs[STG][BN][APAD];
    int tid = threadIdx.x, wid = tid >> 5, lane = tid & 31;
    int wm = wid >> 1, wn = wid & 1;
    int m0 = blockIdx.y * BM, n0 = blockIdx.x * BN;

    uint32_t sA[STG], sB[STG];
#pragma unroll
    for (int s = 0; s < STG; s++) {
        sA[s] = cvta_smem(&As[s][0][0]);
        sB[s] = cvta_smem(&Bs[s][0][0]);
    }

    float c[2][6][4];
#pragma unroll
    for (int mi = 0; mi < 2; mi++)
#pragma unroll
        for (int ni = 0; ni < 6; ni++)
#pragma unroll
            for (int j = 0; j < 4; j++) c[mi][ni][j] = 0.f;

    const int T = K / BK;
    load_tile<NG>(A, W, Nout, K, m0, n0, 0,  sA[0], sB[0], tid);
    load_tile<NG>(A, W, Nout, K, m0, n0, BK, sA[1], sB[1], tid);

    uint32_t aRow = (uint32_t)(wm * 32 + (lane & 15));
    uint32_t aCol8 = (uint32_t)((lane >> 4) * 8);
    int t4 = lane >> 3, r8 = lane & 7;
    uint32_t bBase = (uint32_t)((wn * 48 + (t4 >> 1) * 8 + r8) * APAD + (t4 & 1) * 8);

    for (int t = 0; t < T; t++) {
        asm volatile("cp.async.wait_group 1;" ::: "memory");
        __syncthreads();
        if (t + 2 < T) {
            load_tile<NG>(A, W, Nout, K, m0, n0, (t + 2) * BK,
                          sA[(t + 2) % STG], sB[(t + 2) % STG], tid);
        } else {
            asm volatile("cp.async.commit_group;" ::: "memory");
        }
        int s = t % STG;
#pragma unroll
        for (int ks = 0; ks < 4; ks++) {
            uint32_t a[2][4], b[6][2];
#pragma unroll
            for (int mi = 0; mi < 2; mi++)
                ldm4(a[mi], sA[s] + ((aRow + mi * 16) * APAD + ks * 16 + aCol8) * 2);
#pragma unroll
            for (int nb = 0; nb < 3; nb++) {
                uint32_t bb[4];
                ldm4(bb, sB[s] + (bBase + nb * 16 * APAD + ks * 16) * 2);
                b[nb * 2 + 0][0] = bb[0]; b[nb * 2 + 0][1] = bb[1];
                b[nb * 2 + 1][0] = bb[2]; b[nb * 2 + 1][1] = bb[3];
            }
#pragma unroll
            for (int mi = 0; mi < 2; mi++)
#pragma unroll
                for (int ni = 0; ni < 6; ni++)
                    mma16816(c[mi][ni], a[mi], b[ni]);
        }
    }

    int rbase = m0 + wm * 32 + (lane >> 2);
    int cbase = n0 + wn * 48 + (lane & 3) * 2;
#pragma unroll
    for (int mi = 0; mi < 2; mi++) {
#pragma unroll
        for (int half = 0; half < 2; half++) {
            size_t row = (size_t)(rbase + mi * 16 + half * 8);
#pragma unroll
            for (int ni = 0; ni < 6; ni++) {
                int col = cbase + ni * 8;
                if (!NG || col + 1 < Nout) {
                    float v0 = c[mi][ni][half * 2 + 0];
                    float v1 = c[mi][ni][half * 2 + 1];
                    if (BIAS) { v0 += bias[col]; v1 += bias[col + 1]; }
                    if (GELU) { v0 = gelu_exact(v0); v1 = gelu_exact(v1); }
                    if (RES) {
                        v0 += resid[row * Nout + col];
                        v1 += resid[row * Nout + col + 1];
                    }
                    if (HALFOUT) {
                        *(__half2*)((__half*)Cout + row * Nout + col) =
                            __floats2half2_rn(v0, v1);
                    } else {
                        *(float2*)((float*)Cout + row * Nout + col) =
                            make_float2(v0, v1);
                    }
                }
            }
        }
    }
}

// ---------------- Host launcher ----------------
extern "C" void kernel_launch(void* const* d_in, const int* in_sizes, int n_in,
                              void* d_out, int out_size) {
    const float* x      = (const float*)d_in[0];
    const float* qkv_w  = (const float*)d_in[1];
    const float* scale  = (const float*)d_in[2];
    const float* out_w  = (const float*)d_in[3];
    const float* out_b  = (const float*)d_in[4];
    const float* ln1_w  = (const float*)d_in[5];
    const float* ln1_b  = (const float*)d_in[6];
    const float* ln2_w  = (const float*)d_in[7];
    const float* ln2_b  = (const float*)d_in[8];
    const float* fc1_w  = (const float*)d_in[9];
    const float* fc1_b  = (const float*)d_in[10];
    const float* fc2_w  = (const float*)d_in[11];
    const float* fc2_b  = (const float*)d_in[12];
    const float* norm_w = (const float*)d_in[13];
    const float* norm_b = (const float*)d_in[14];
    const float* head_w = (const float*)d_in[15];
    const float* head_b = (const float*)d_in[16];
    float* out = (float*)d_out;

    float  *h;
    __half *y, *qkv, *o, *m, *cls, *w16;
    cudaGetSymbolAddress((void**)&h,   g_h);
    cudaGetSymbolAddress((void**)&y,   g_y);
    cudaGetSymbolAddress((void**)&qkv, g_qkv);
    cudaGetSymbolAddress((void**)&o,   g_o);
    cudaGetSymbolAddress((void**)&m,   g_m);
    cudaGetSymbolAddress((void**)&cls, g_cls);
    cudaGetSymbolAddress((void**)&w16, g_w16);

    cudaMemcpyAsync(h, x, sizeof(float) * (size_t)RROWS * Dm, cudaMemcpyDeviceToDevice);

    convert_all<<<4096, 256>>>(qkv_w, out_w, fc1_w, fc2_w, head_w, w16);

    dim3 gQKV(3 * Dm / BN, RROWS / BM);   // (18, 248)
    dim3 gPROJ(Dm / BN, RROWS / BM);      // (6, 248)
    dim3 gFC1(FF / BN, RROWS / BM);       // (24, 248)
    dim3 gATT(Bz, Hh);
    int lnBlocks = RROWS / 8;

    for (int l = 0; l < Ll; l++) {
        const __half* qw = w16 + OQKV + (size_t)l * 3 * Dm * Dm;
        const __half* ow = w16 + OOUT + (size_t)l * Dm * Dm;
        const __half* w1 = w16 + OFC1 + (size_t)l * FF * Dm;
        const __half* w2 = w16 + OFC2 + (size_t)l * Dm * FF;

        ln_kernel<<<lnBlocks, 256>>>(h, ln1_w + l * Dm, ln1_b + l * Dm, y, RROWS, Dm);
        hgemm<false, false, false, true, false><<<gQKV, 256>>>(
            y, qw, nullptr, nullptr, qkv, RROWS, 3 * Dm, Dm);
        attn_kernel<<<gATT, 128>>>(qkv, scale + l * Hh, o);
        hgemm<true, true, false, false, false><<<gPROJ, 256>>>(
            o, ow, out_b + l * Dm, h, h, RROWS, Dm, Dm);
        ln_kernel<<<lnBlocks, 256>>>(h, ln2_w + l * Dm, ln2_b + l * Dm, y, RROWS, Dm);
        hgemm<true, false, true, true, false><<<gFC1, 256>>>(
            y, w1, fc1_b + l * FF, nullptr, m, RROWS, FF, Dm);
        hgemm<true, true, false, false, false><<<gPROJ, 256>>>(
            m, w2, fc2_b + l * Dm, h, h, RROWS, Dm, FF);
    }

    ln_kernel<<<Bz / 8, 256>>>(h, norm_w, norm_b, cls, Bz, (long long)Nt * Dm);
    dim3 gHEAD((NC + BN - 1) / BN, Bz / BM); // (11, 8)
    hgemm<true, false, false, false, true><<<gHEAD, 256>>>(
        cls, w16 + OHEAD, head_b, nullptr, out, Bz, NC, Dm);
}

// round 10
// speedup vs baseline: 5.8557x; 1.0428x over previous
#include <cuda_runtime.h>
#include <cuda_fp16.h>
#include <math.h>
#include <stdint.h>

// ---------------- Problem constants ----------------
#define Bz   1024
#define Nt   31
#define Dm   576
#define Hh   16
#define Ll   12
#define DH   36
#define FF   2304
#define NC   1000
#define EPSV 1e-5f
#define NEGV -987654321.0f
#define RROWS (Bz * Nt) // 31744

// ---------------- Scratch ----------------
__device__ float  g_h  [(size_t)RROWS * Dm];
__device__ __half g_y  [(size_t)RROWS * Dm];
__device__ __half g_qkv[(size_t)RROWS * 3 * Dm];
__device__ __half g_o  [(size_t)RROWS * Dm];
__device__ __half g_m  [(size_t)RROWS * FF];
__device__ __half g_cls[(size_t)Bz * Dm];

// fp16 weight arena
#define OQKV  0
#define OOUT  11943936
#define OFC1  15925248
#define OFC2  31850496
#define OHEAD 47775744
#define WTOT  48351744
__device__ __half g_w16[WTOT];

// ---------------- helpers ----------------
__device__ __forceinline__ uint32_t cvta_smem(const void* p) {
    uint32_t a;
    asm("{ .reg .u64 t; cvta.to.shared.u64 t, %1; cvt.u32.u64 %0, t; }" : "=r"(a) : "l"(p));
    return a;
}
__device__ __forceinline__ void cpasync16(uint32_t dst, const void* src, uint32_t srcsize) {
    asm volatile("cp.async.cg.shared.global [%0], [%1], 16, %2;"
                 :: "r"(dst), "l"(src), "r"(srcsize));
}
__device__ __forceinline__ void ldm4(uint32_t* a, uint32_t addr) {
    asm volatile("ldmatrix.sync.aligned.m8n8.x4.shared.b16 {%0,%1,%2,%3}, [%4];"
                 : "=r"(a[0]), "=r"(a[1]), "=r"(a[2]), "=r"(a[3]) : "r"(addr));
}
__device__ __forceinline__ void mma16816(float* c, const uint32_t* a, const uint32_t* b) {
    asm volatile(
        "mma.sync.aligned.m16n8k16.row.col.f32.f16.f16.f32 "
        "{%0,%1,%2,%3}, {%4,%5,%6,%7}, {%8,%9}, {%0,%1,%2,%3};"
        : "+f"(c[0]), "+f"(c[1]), "+f"(c[2]), "+f"(c[3])
        : "r"(a[0]), "r"(a[1]), "r"(a[2]), "r"(a[3]), "r"(b[0]), "r"(b[1]));
}
__device__ __forceinline__ float gelu_exact(float x) {
    return 0.5f * x * (1.0f + erff(x * 0.70710678118654752f));
}

// ---------------- fused convert fp32 -> fp16 (single launch) ----------------
__global__ void convert_all(const float* __restrict__ qkv_w,
                            const float* __restrict__ out_w,
                            const float* __restrict__ fc1_w,
                            const float* __restrict__ fc2_w,
                            const float* __restrict__ head_w,
                            __half* __restrict__ w) {
    int stride = gridDim.x * blockDim.x;
    for (size_t i = blockIdx.x * blockDim.x + threadIdx.x; i < WTOT; i += stride) {
        float v;
        if (i < OOUT)       v = qkv_w[i - OQKV];
        else if (i < OFC1)  v = out_w[i - OOUT];
        else if (i < OFC2)  v = fc1_w[i - OFC1];
        else if (i < OHEAD) v = fc2_w[i - OFC2];
        else                v = head_w[i - OHEAD];
        w[i] = __float2half_rn(v);
    }
}

// ---------------- LayerNorm (fp32 in, fp16 out) ----------------
__global__ void ln_kernel(const float* __restrict__ x,
                          const float* __restrict__ w,
                          const float* __restrict__ b,
                          __half* __restrict__ y,
                          int rows, long long in_row_stride) {
    int row = blockIdx.x * (blockDim.x >> 5) + (threadIdx.x >> 5);
    if (row >= rows) return;
    int lane = threadIdx.x & 31;
    const float* xr = x + (long long)row * in_row_stride;
    float v[18];
    float s = 0.f;
#pragma unroll
    for (int i = 0; i < 18; i++) { v[i] = xr[lane + i * 32]; s += v[i]; }
#pragma unroll
    for (int o = 16; o; o >>= 1) s += __shfl_xor_sync(0xffffffffu, s, o);
    float mean = s * (1.0f / Dm);
    float s2 = 0.f;
#pragma unroll
    for (int i = 0; i < 18; i++) { float d = v[i] - mean; s2 += d * d; }
#pragma unroll
    for (int o = 16; o; o >>= 1) s2 += __shfl_xor_sync(0xffffffffu, s2, o);
    float inv = rsqrtf(s2 * (1.0f / Dm) + EPSV);
    __half* yr = y + (long long)row * Dm;
#pragma unroll
    for (int i = 0; i < 18; i++) {
        int d = lane + i * 32;
        yr[d] = __float2half_rn((v[i] - mean) * inv * w[d] + b[d]);
    }
}

// ---------------- Attention: register-tiled, one block per (batch, head) ----------
#define QP 37
#define SP 33

__global__ void attn_kernel(const __half* __restrict__ qkv,
                            const float* __restrict__ scale,
                            __half* __restrict__ o) {
    int b = blockIdx.x;
    int h = blockIdx.y;
    __shared__ float qs[32][QP];
    __shared__ float ks[32][QP];
    __shared__ float vs[32][QP];
    __shared__ float ss[32][SP];
    int tid = threadIdx.x; // 128

    const __half2* base2 = (const __half2*)(qkv + (long long)b * Nt * (3 * Dm) + h * DH);
    for (int idx = tid; idx < 32 * (DH / 2); idx += 128) {
        int n = idx / (DH / 2), dp = idx % (DH / 2);
        float2 qf = make_float2(0.f, 0.f), kf = qf, vf = qf;
        if (n < Nt) {
            const __half2* p = base2 + (long long)n * (3 * Dm / 2) + dp;
            qf = __half22float2(p[0]);
            kf = __half22float2(p[Dm / 2]);
            vf = __half22float2(p[Dm]);
        }
        qs[n][2 * dp] = qf.x; qs[n][2 * dp + 1] = qf.y;
        ks[n][2 * dp] = kf.x; ks[n][2 * dp + 1] = kf.y;
        vs[n][2 * dp] = vf.x; vs[n][2 * dp + 1] = vf.y;
    }
    __syncthreads();

    float sc = scale[h];

    // ---- QK: 16(i) x 8(j); per-thread 2 rows x 4 cols ----
    {
        int ti = tid >> 3, tj = tid & 7;
        int i0 = ti, i1 = ti + 16, j0 = tj * 4;
        float acc[2][4];
#pragma unroll
        for (int r = 0; r < 2; r++)
#pragma unroll
            for (int jj = 0; jj < 4; jj++) acc[r][jj] = 0.f;
#pragma unroll
        for (int d = 0; d < DH; d++) {
            float q0 = qs[i0][d], q1 = qs[i1][d];
#pragma unroll
            for (int jj = 0; jj < 4; jj++) {
                float kv = ks[j0 + jj][d];
                acc[0][jj] = fmaf(q0, kv, acc[0][jj]);
                acc[1][jj] = fmaf(q1, kv, acc[1][jj]);
            }
        }
#pragma unroll
        for (int r = 0; r < 2; r++) {
            int i = (r == 0) ? i0 : i1;
#pragma unroll
            for (int jj = 0; jj < 4; jj++) {
                int j = j0 + jj;
                ss[i][j] = (i == j) ? NEGV : acc[r][jj] * sc;
            }
        }
    }
    __syncthreads();

    // ---- softmax: all 128 threads (32 rows x 4 lanes) ----
    {
        int i = tid >> 2, q = tid & 3;
        int jb = q * 8;
        float mx = -3.4e38f;
#pragma unroll
        for (int jj = 0; jj < 8; jj++) {
            int j = jb + jj;
            if (j < Nt) mx = fmaxf(mx, ss[i][j]);
        }
        mx = fmaxf(mx, __shfl_xor_sync(0xffffffffu, mx, 1));
        mx = fmaxf(mx, __shfl_xor_sync(0xffffffffu, mx, 2));
        float e[8];
        float sum = 0.f;
#pragma unroll
        for (int jj = 0; jj < 8; jj++) {
            int j = jb + jj;
            if (j < Nt) { e[jj] = expf(ss[i][j] - mx); sum += e[jj]; }
            else e[jj] = 0.f;
        }
        sum += __shfl_xor_sync(0xffffffffu, sum, 1);
        sum += __shfl_xor_sync(0xffffffffu, sum, 2);
        float inv = 1.0f / sum;
        __syncthreads();
#pragma unroll
        for (int jj = 0; jj < 8; jj++) {
            int j = jb + jj;
            ss[i][j] = e[jj] * inv;
        }
    }
    __syncthreads();

    // ---- AV: 8(i) x 16(d); per-thread 4 rows x 2 d (x2 chunks) ----
    {
        int ti = tid >> 4, tdp = tid & 15;
#pragma unroll
        for (int c = 0; c < 2; c++) {
            int d = 2 * (tdp + 16 * c);
            if (d < DH) {
                float a[4][2];
#pragma unroll
                for (int r = 0; r < 4; r++) { a[r][0] = 0.f; a[r][1] = 0.f; }
#pragma unroll
                for (int j = 0; j < 32; j++) {
                    float v0 = vs[j][d], v1 = vs[j][d + 1];
#pragma unroll
                    for (int r = 0; r < 4; r++) {
                        float w = ss[ti + 8 * r][j];
                        a[r][0] = fmaf(w, v0, a[r][0]);
                        a[r][1] = fmaf(w, v1, a[r][1]);
                    }
                }
#pragma unroll
                for (int r = 0; r < 4; r++) {
                    int i = ti + 8 * r;
                    if (i < Nt) {
                        *(__half2*)(o + (long long)(b * Nt + i) * Dm + h * DH + d) =
                            __floats2half2_rn(a[r][0], a[r][1]);
                    }
                }
            }
        }
    }
}

// ---------------- HMMA GEMM: C[M,Nout] = A[M,K] * W[Nout,K]^T ----------------
// BM=128, BN=96, BK=64, STG=3; 4 warps (128 threads), 2m x 2n, warp tile 64x48.
#define BM 128
#define BN 96
#define BK 64
#define STG 3
#define APAD 72
#define GT 128   // threads per GEMM block

template <bool NG>
__device__ __forceinline__ void load_tile(const __half* A, const __half* W,
                                          int Nout, int K, int m0, int n0, int k0,
                                          uint32_t sa, uint32_t sb, int tid) {
    // A: 128 rows x 8 chunks = 1024 chunks, 128 threads -> 8 iters
#pragma unroll
    for (int i = 0; i < 8; i++) {
        int idx = tid + i * GT;
        int r = idx >> 3, ch = idx & 7;
        const __half* g = A + (size_t)(m0 + r) * K + k0 + ch * 8;
        cpasync16(sa + r * (APAD * 2) + ch * 16, g, 16);
    }
    // B: 96 rows x 8 chunks = 768 chunks -> 6 iters
#pragma unroll
    for (int i = 0; i < 6; i++) {
        int idx = tid + i * GT;
        int r = idx >> 3, ch = idx & 7;
        int rr = n0 + r;
        uint32_t sz = 16;
        if (NG && rr >= Nout) { rr = 0; sz = 0; }
        const __half* g = W + (size_t)rr * K + k0 + ch * 8;
        cpasync16(sb + r * (APAD * 2) + ch * 16, g, sz);
    }
    asm volatile("cp.async.commit_group;" ::: "memory");
}

template <bool BIAS, bool RES, bool GELU, bool HALFOUT, bool NG>
__global__ __launch_bounds__(GT) void hgemm(
    const __half* __restrict__ A, const __half* __restrict__ W,
    const float* __restrict__ bias, const float* __restrict__ resid,
    void* __restrict__ Cout, int M, int Nout, int K) {
    __shared__ __half As[STG][BM][APAD];
    __shared__ __half Bs[STG][BN][APAD];
    int tid = threadIdx.x, wid = tid >> 5, lane = tid & 31;
    int wm = wid >> 1, wn = wid & 1;
    int m0 = blockIdx.y * BM, n0 = blockIdx.x * BN;

    uint32_t sA[STG], sB[STG];
#pragma unroll
    for (int s = 0; s < STG; s++) {
        sA[s] = cvta_smem(&As[s][0][0]);
        sB[s] = cvta_smem(&Bs[s][0][0]);
    }

    float c[4][6][4];
#pragma unroll
    for (int mi = 0; mi < 4; mi++)
#pragma unroll
        for (int ni = 0; ni < 6; ni++)
#pragma unroll
            for (int j = 0; j < 4; j++) c[mi][ni][j] = 0.f;

    const int T = K / BK;
    load_tile<NG>(A, W, Nout, K, m0, n0, 0,  sA[0], sB[0], tid);
    load_tile<NG>(A, W, Nout, K, m0, n0, BK, sA[1], sB[1], tid);

    uint32_t aRow = (uint32_t)(wm * 64 + (lane & 15));
    uint32_t aCol8 = (uint32_t)((lane >> 4) * 8);
    int t4 = lane >> 3, r8 = lane & 7;
    uint32_t bBase = (uint32_t)((wn * 48 + (t4 >> 1) * 8 + r8) * APAD + (t4 & 1) * 8);

    for (int t = 0; t < T; t++) {
        asm volatile("cp.async.wait_group 1;" ::: "memory");
        __syncthreads();
        if (t + 2 < T) {
            load_tile<NG>(A, W, Nout, K, m0, n0, (t + 2) * BK,
                          sA[(t + 2) % STG], sB[(t + 2) % STG], tid);
        } else {
            asm volatile("cp.async.commit_group;" ::: "memory");
        }
        int s = t % STG;
#pragma unroll
        for (int ks = 0; ks < 4; ks++) {
            uint32_t a[4][4], b[6][2];
#pragma unroll
            for (int mi = 0; mi < 4; mi++)
                ldm4(a[mi], sA[s] + ((aRow + mi * 16) * APAD + ks * 16 + aCol8) * 2);
#pragma unroll
            for (int nb = 0; nb < 3; nb++) {
                uint32_t bb[4];
                ldm4(bb, sB[s] + (bBase + nb * 16 * APAD + ks * 16) * 2);
                b[nb * 2 + 0][0] = bb[0]; b[nb * 2 + 0][1] = bb[1];
                b[nb * 2 + 1][0] = bb[2]; b[nb * 2 + 1][1] = bb[3];
            }
#pragma unroll
            for (int mi = 0; mi < 4; mi++)
#pragma unroll
                for (int ni = 0; ni < 6; ni++)
                    mma16816(c[mi][ni], a[mi], b[ni]);
        }
    }

    int rbase = m0 + wm * 64 + (lane >> 2);
    int cbase = n0 + wn * 48 + (lane & 3) * 2;
#pragma unroll
    for (int mi = 0; mi < 4; mi++) {
#pragma unroll
        for (int half = 0; half < 2; half++) {
            size_t row = (size_t)(rbase + mi * 16 + half * 8);
#pragma unroll
            for (int ni = 0; ni < 6; ni++) {
                int col = cbase + ni * 8;
                if (!NG || col + 1 < Nout) {
                    float v0 = c[mi][ni][half * 2 + 0];
                    float v1 = c[mi][ni][half * 2 + 1];
                    if (BIAS) { v0 += bias[col]; v1 += bias[col + 1]; }
                    if (GELU) { v0 = gelu_exact(v0); v1 = gelu_exact(v1); }
                    if (RES) {
                        v0 += resid[row * Nout + col];
                        v1 += resid[row * Nout + col + 1];
                    }
                    if (HALFOUT) {
                        *(__half2*)((__half*)Cout + row * Nout + col) =
                            __floats2half2_rn(v0, v1);
                    } else {
                        *(float2*)((float*)Cout + row * Nout + col) =
                            make_float2(v0, v1);
                    }
                }
            }
        }
    }
}

// ---------------- Host launcher ----------------
extern "C" void kernel_launch(void* const* d_in, const int* in_sizes, int n_in,
                              void* d_out, int out_size) {
    const float* x      = (const float*)d_in[0];
    const float* qkv_w  = (const float*)d_in[1];
    const float* scale  = (const float*)d_in[2];
    const float* out_w  = (const float*)d_in[3];
    const float* out_b  = (const float*)d_in[4];
    const float* ln1_w  = (const float*)d_in[5];
    const float* ln1_b  = (const float*)d_in[6];
    const float* ln2_w  = (const float*)d_in[7];
    const float* ln2_b  = (const float*)d_in[8];
    const float* fc1_w  = (const float*)d_in[9];
    const float* fc1_b  = (const float*)d_in[10];
    const float* fc2_w  = (const float*)d_in[11];
    const float* fc2_b  = (const float*)d_in[12];
    const float* norm_w = (const float*)d_in[13];
    const float* norm_b = (const float*)d_in[14];
    const float* head_w = (const float*)d_in[15];
    const float* head_b = (const float*)d_in[16];
    float* out = (float*)d_out;

    float  *h;
    __half *y, *qkv, *o, *m, *cls, *w16;
    cudaGetSymbolAddress((void**)&h,   g_h);
    cudaGetSymbolAddress((void**)&y,   g_y);
    cudaGetSymbolAddress((void**)&qkv, g_qkv);
    cudaGetSymbolAddress((void**)&o,   g_o);
    cudaGetSymbolAddress((void**)&m,   g_m);
    cudaGetSymbolAddress((void**)&cls, g_cls);
    cudaGetSymbolAddress((void**)&w16, g_w16);

    cudaMemcpyAsync(h, x, sizeof(float) * (size_t)RROWS * Dm, cudaMemcpyDeviceToDevice);

    convert_all<<<4096, 256>>>(qkv_w, out_w, fc1_w, fc2_w, head_w, w16);

    dim3 gQKV(3 * Dm / BN, RROWS / BM);   // (18, 248)
    dim3 gPROJ(Dm / BN, RROWS / BM);      // (6, 248)
    dim3 gFC1(FF / BN, RROWS / BM);       // (24, 248)
    dim3 gATT(Bz, Hh);
    int lnBlocks = RROWS / 8;

    for (int l = 0; l < Ll; l++) {
        const __half* qw = w16 + OQKV + (size_t)l * 3 * Dm * Dm;
        const __half* ow = w16 + OOUT + (size_t)l * Dm * Dm;
        const __half* w1 = w16 + OFC1 + (size_t)l * FF * Dm;
        const __half* w2 = w16 + OFC2 + (size_t)l * Dm * FF;

        ln_kernel<<<lnBlocks, 256>>>(h, ln1_w + l * Dm, ln1_b + l * Dm, y, RROWS, Dm);
        hgemm<false, false, false, true, false><<<gQKV, GT>>>(
            y, qw, nullptr, nullptr, qkv, RROWS, 3 * Dm, Dm);
        attn_kernel<<<gATT, 128>>>(qkv, scale + l * Hh, o);
        hgemm<true, true, false, false, false><<<gPROJ, GT>>>(
            o, ow, out_b + l * Dm, h, h, RROWS, Dm, Dm);
        ln_kernel<<<lnBlocks, 256>>>(h, ln2_w + l * Dm, ln2_b + l * Dm, y, RROWS, Dm);
        hgemm<true, false, true, true, false><<<gFC1, GT>>>(
            y, w1, fc1_b + l * FF, nullptr, m, RROWS, FF, Dm);
        hgemm<true, true, false, false, false><<<gPROJ, GT>>>(
            m, w2, fc2_b + l * Dm, h, h, RROWS, Dm, FF);
    }

    ln_kernel<<<Bz / 8, 256>>>(h, norm_w, norm_b, cls, Bz, (long long)Nt * Dm);
    dim3 gHEAD((NC + BN - 1) / BN, Bz / BM); // (11, 8)
    hgemm<true, false, false, false, true><<<gHEAD, GT>>>(
        cls, w16 + OHEAD, head_b, nullptr, out, Bz, NC, Dm);
}

// round 11
// speedup vs baseline: 6.6241x; 1.1312x over previous
#include <cuda_runtime.h>
#include <cuda_fp16.h>
#include <math.h>
#include <stdint.h>

// ---------------- Problem constants ----------------
#define Bz   1024
#define Nt   31
#define Dm   576
#define Hh   16
#define Ll   12
#define DH   36
#define FF   2304
#define NC   1000
#define EPSV 1e-5f
#define NEGV -987654321.0f
#define RROWS (Bz * Nt) // 31744

// ---------------- Scratch ----------------
__device__ float  g_h  [(size_t)RROWS * Dm];
__device__ __half g_y  [(size_t)RROWS * Dm];
__device__ __half g_qkv[(size_t)RROWS * 3 * Dm];
__device__ __half g_o  [(size_t)RROWS * Dm];
__device__ __half g_m  [(size_t)RROWS * FF];
__device__ __half g_cls[(size_t)Bz * Dm];

// fp16 weight arena
#define OQKV  0
#define OOUT  11943936
#define OFC1  15925248
#define OFC2  31850496
#define OHEAD 47775744
#define WTOT  48351744
__device__ __half g_w16[WTOT];

// ---------------- helpers ----------------
__device__ __forceinline__ uint32_t cvta_smem(const void* p) {
    uint32_t a;
    asm("{ .reg .u64 t; cvta.to.shared.u64 t, %1; cvt.u32.u64 %0, t; }" : "=r"(a) : "l"(p));
    return a;
}
__device__ __forceinline__ void cpasync16(uint32_t dst, const void* src, uint32_t srcsize) {
    asm volatile("cp.async.cg.shared.global [%0], [%1], 16, %2;"
                 :: "r"(dst), "l"(src), "r"(srcsize));
}
__device__ __forceinline__ void ldm4(uint32_t* a, uint32_t addr) {
    asm volatile("ldmatrix.sync.aligned.m8n8.x4.shared.b16 {%0,%1,%2,%3}, [%4];"
                 : "=r"(a[0]), "=r"(a[1]), "=r"(a[2]), "=r"(a[3]) : "r"(addr));
}
__device__ __forceinline__ void mma16816(float* c, const uint32_t* a, const uint32_t* b) {
    asm volatile(
        "mma.sync.aligned.m16n8k16.row.col.f32.f16.f16.f32 "
        "{%0,%1,%2,%3}, {%4,%5,%6,%7}, {%8,%9}, {%0,%1,%2,%3};"
        : "+f"(c[0]), "+f"(c[1]), "+f"(c[2]), "+f"(c[3])
        : "r"(a[0]), "r"(a[1]), "r"(a[2]), "r"(a[3]), "r"(b[0]), "r"(b[1]));
}
__device__ __forceinline__ float gelu_exact(float x) {
    return 0.5f * x * (1.0f + erff(x * 0.70710678118654752f));
}

// ---------------- fused convert fp32 -> fp16 (single launch) ----------------
__global__ void convert_all(const float* __restrict__ qkv_w,
                            const float* __restrict__ out_w,
                            const float* __restrict__ fc1_w,
                            const float* __restrict__ fc2_w,
                            const float* __restrict__ head_w,
                            __half* __restrict__ w) {
    int stride = gridDim.x * blockDim.x;
    for (size_t i = blockIdx.x * blockDim.x + threadIdx.x; i < WTOT; i += stride) {
        float v;
        if (i < OOUT)       v = qkv_w[i - OQKV];
        else if (i < OFC1)  v = out_w[i - OOUT];
        else if (i < OFC2)  v = fc1_w[i - OFC1];
        else if (i < OHEAD) v = fc2_w[i - OFC2];
        else                v = head_w[i - OHEAD];
        w[i] = __float2half_rn(v);
    }
}

// ---------------- LayerNorm (fp32 in, fp16 out) ----------------
__global__ void ln_kernel(const float* __restrict__ x,
                          const float* __restrict__ w,
                          const float* __restrict__ b,
                          __half* __restrict__ y,
                          int rows, long long in_row_stride) {
    int row = blockIdx.x * (blockDim.x >> 5) + (threadIdx.x >> 5);
    if (row >= rows) return;
    int lane = threadIdx.x & 31;
    const float* xr = x + (long long)row * in_row_stride;
    float v[18];
    float s = 0.f;
#pragma unroll
    for (int i = 0; i < 18; i++) { v[i] = xr[lane + i * 32]; s += v[i]; }
#pragma unroll
    for (int o = 16; o; o >>= 1) s += __shfl_xor_sync(0xffffffffu, s, o);
    float mean = s * (1.0f / Dm);
    float s2 = 0.f;
#pragma unroll
    for (int i = 0; i < 18; i++) { float d = v[i] - mean; s2 += d * d; }
#pragma unroll
    for (int o = 16; o; o >>= 1) s2 += __shfl_xor_sync(0xffffffffu, s2, o);
    float inv = rsqrtf(s2 * (1.0f / Dm) + EPSV);
    __half* yr = y + (long long)row * Dm;
#pragma unroll
    for (int i = 0; i < 18; i++) {
        int d = lane + i * 32;
        yr[d] = __float2half_rn((v[i] - mean) * inv * w[d] + b[d]);
    }
}

// ---------------- Attention: register-tiled, one block per (batch, head) ----------
#define QP 37
#define SP 33

__global__ __launch_bounds__(128, 5)
void attn_kernel(const __half* __restrict__ qkv,
                 const float* __restrict__ scale,
                 __half* __restrict__ o) {
    int b = blockIdx.x;
    int h = blockIdx.y;
    __shared__ float qs[32][QP];
    __shared__ float ks[32][QP];
    __shared__ float vs[32][QP];
    __shared__ float ss[32][SP];
    int tid = threadIdx.x; // 128

    const __half2* base2 = (const __half2*)(qkv + (long long)b * Nt * (3 * Dm) + h * DH);
    for (int idx = tid; idx < 32 * (DH / 2); idx += 128) {
        int n = idx / (DH / 2), dp = idx % (DH / 2);
        float2 qf = make_float2(0.f, 0.f), kf = qf, vf = qf;
        if (n < Nt) {
            const __half2* p = base2 + (long long)n * (3 * Dm / 2) + dp;
            qf = __half22float2(p[0]);
            kf = __half22float2(p[Dm / 2]);
            vf = __half22float2(p[Dm]);
        }
        qs[n][2 * dp] = qf.x; qs[n][2 * dp + 1] = qf.y;
        ks[n][2 * dp] = kf.x; ks[n][2 * dp + 1] = kf.y;
        vs[n][2 * dp] = vf.x; vs[n][2 * dp + 1] = vf.y;
    }
    __syncthreads();

    float sc = scale[h];

    // ---- QK: 16(i) x 8(j); per-thread 2 rows x 4 cols ----
    {
        int ti = tid >> 3, tj = tid & 7;
        int i0 = ti, i1 = ti + 16, j0 = tj * 4;
        float acc[2][4];
#pragma unroll
        for (int r = 0; r < 2; r++)
#pragma unroll
            for (int jj = 0; jj < 4; jj++) acc[r][jj] = 0.f;
#pragma unroll
        for (int d = 0; d < DH; d++) {
            float q0 = qs[i0][d], q1 = qs[i1][d];
#pragma unroll
            for (int jj = 0; jj < 4; jj++) {
                float kv = ks[j0 + jj][d];
                acc[0][jj] = fmaf(q0, kv, acc[0][jj]);
                acc[1][jj] = fmaf(q1, kv, acc[1][jj]);
            }
        }
#pragma unroll
        for (int r = 0; r < 2; r++) {
            int i = (r == 0) ? i0 : i1;
#pragma unroll
            for (int jj = 0; jj < 4; jj++) {
                int j = j0 + jj;
                ss[i][j] = (i == j) ? NEGV : acc[r][jj] * sc;
            }
        }
    }
    __syncthreads();

    // ---- softmax: all 128 threads (32 rows x 4 lanes) ----
    {
        int i = tid >> 2, q = tid & 3;
        int jb = q * 8;
        float mx = -3.4e38f;
#pragma unroll
        for (int jj = 0; jj < 8; jj++) {
            int j = jb + jj;
            if (j < Nt) mx = fmaxf(mx, ss[i][j]);
        }
        mx = fmaxf(mx, __shfl_xor_sync(0xffffffffu, mx, 1));
        mx = fmaxf(mx, __shfl_xor_sync(0xffffffffu, mx, 2));
        float e[8];
        float sum = 0.f;
#pragma unroll
        for (int jj = 0; jj < 8; jj++) {
            int j = jb + jj;
            if (j < Nt) { e[jj] = expf(ss[i][j] - mx); sum += e[jj]; }
            else e[jj] = 0.f;
        }
        sum += __shfl_xor_sync(0xffffffffu, sum, 1);
        sum += __shfl_xor_sync(0xffffffffu, sum, 2);
        float inv = 1.0f / sum;
        __syncthreads();
#pragma unroll
        for (int jj = 0; jj < 8; jj++) {
            int j = jb + jj;
            ss[i][j] = e[jj] * inv;
        }
    }
    __syncthreads();

    // ---- AV: 8(i) x 16(d); per-thread 4 rows x 2 d (x2 chunks) ----
    {
        int ti = tid >> 4, tdp = tid & 15;
#pragma unroll
        for (int c = 0; c < 2; c++) {
            int d = 2 * (tdp + 16 * c);
            if (d < DH) {
                float a[4][2];
#pragma unroll
                for (int r = 0; r < 4; r++) { a[r][0] = 0.f; a[r][1] = 0.f; }
#pragma unroll
                for (int j = 0; j < 32; j++) {
                    float v0 = vs[j][d], v1 = vs[j][d + 1];
#pragma unroll
                    for (int r = 0; r < 4; r++) {
                        float w = ss[ti + 8 * r][j];
                        a[r][0] = fmaf(w, v0, a[r][0]);
                        a[r][1] = fmaf(w, v1, a[r][1]);
                    }
                }
#pragma unroll
                for (int r = 0; r < 4; r++) {
                    int i = ti + 8 * r;
                    if (i < Nt) {
                        *(__half2*)(o + (long long)(b * Nt + i) * Dm + h * DH + d) =
                            __floats2half2_rn(a[r][0], a[r][1]);
                    }
                }
            }
        }
    }
}

// ---------------- HMMA GEMM: C[M,Nout] = A[M,K] * W[Nout,K]^T ----------------
// BM=128, BN=96, BK=64, STG=2 (double-buffer, 63KB smem -> 3 CTA/SM),
// 4 warps (128 threads), 2m x 2n, warp tile 64x48.
#define BM 128
#define BN 96
#define BK 64
#define STG 2
#define APAD 72
#define GT 128

template <bool NG>
__device__ __forceinline__ void load_tile(const __half* A, const __half* W,
                                          int Nout, int K, int m0, int n0, int k0,
                                          uint32_t sa, uint32_t sb, int tid) {
#pragma unroll
    for (int i = 0; i < 8; i++) {
        int idx = tid + i * GT;
        int r = idx >> 3, ch = idx & 7;
        const __half* g = A + (size_t)(m0 + r) * K + k0 + ch * 8;
        cpasync16(sa + r * (APAD * 2) + ch * 16, g, 16);
    }
#pragma unroll
    for (int i = 0; i < 6; i++) {
        int idx = tid + i * GT;
        int r = idx >> 3, ch = idx & 7;
        int rr = n0 + r;
        uint32_t sz = 16;
        if (NG && rr >= Nout) { rr = 0; sz = 0; }
        const __half* g = W + (size_t)rr * K + k0 + ch * 8;
        cpasync16(sb + r * (APAD * 2) + ch * 16, g, sz);
    }
    asm volatile("cp.async.commit_group;" ::: "memory");
}

template <bool BIAS, bool RES, bool GELU, bool HALFOUT, bool NG>
__global__ __launch_bounds__(GT, 3) void hgemm(
    const __half* __restrict__ A, const __half* __restrict__ W,
    const float* __restrict__ bias, const float* __restrict__ resid,
    void* __restrict__ Cout, int M, int Nout, int K) {
    __shared__ __half As[STG][BM][APAD];
    __shared__ __half Bs[STG][BN][APAD];
    int tid = threadIdx.x, wid = tid >> 5, lane = tid & 31;
    int wm = wid >> 1, wn = wid & 1;
    int m0 = blockIdx.y * BM, n0 = blockIdx.x * BN;

    uint32_t sA[STG], sB[STG];
#pragma unroll
    for (int s = 0; s < STG; s++) {
        sA[s] = cvta_smem(&As[s][0][0]);
        sB[s] = cvta_smem(&Bs[s][0][0]);
    }

    float c[4][6][4];
#pragma unroll
    for (int mi = 0; mi < 4; mi++)
#pragma unroll
        for (int ni = 0; ni < 6; ni++)
#pragma unroll
            for (int j = 0; j < 4; j++) c[mi][ni][j] = 0.f;

    const int T = K / BK;
    load_tile<NG>(A, W, Nout, K, m0, n0, 0, sA[0], sB[0], tid);

    uint32_t aRow = (uint32_t)(wm * 64 + (lane & 15));
    uint32_t aCol8 = (uint32_t)((lane >> 4) * 8);
    int t4 = lane >> 3, r8 = lane & 7;
    uint32_t bBase = (uint32_t)((wn * 48 + (t4 >> 1) * 8 + r8) * APAD + (t4 & 1) * 8);

    for (int t = 0; t < T; t++) {
        asm volatile("cp.async.wait_group 0;" ::: "memory");
        __syncthreads();   // tile t ready for all; all warps done computing t-1
        if (t + 1 < T) {
            // buffer (t+1)&1 was compute buffer of t-1; barrier above makes reuse safe
            load_tile<NG>(A, W, Nout, K, m0, n0, (t + 1) * BK,
                          sA[(t + 1) & 1], sB[(t + 1) & 1], tid);
        }
        int s = t & 1;
#pragma unroll
        for (int ks = 0; ks < 4; ks++) {
            uint32_t a[4][4], b[6][2];
#pragma unroll
            for (int mi = 0; mi < 4; mi++)
                ldm4(a[mi], sA[s] + ((aRow + mi * 16) * APAD + ks * 16 + aCol8) * 2);
#pragma unroll
            for (int nb = 0; nb < 3; nb++) {
                uint32_t bb[4];
                ldm4(bb, sB[s] + (bBase + nb * 16 * APAD + ks * 16) * 2);
                b[nb * 2 + 0][0] = bb[0]; b[nb * 2 + 0][1] = bb[1];
                b[nb * 2 + 1][0] = bb[2]; b[nb * 2 + 1][1] = bb[3];
            }
#pragma unroll
            for (int mi = 0; mi < 4; mi++)
#pragma unroll
                for (int ni = 0; ni < 6; ni++)
                    mma16816(c[mi][ni], a[mi], b[ni]);
        }
    }

    int rbase = m0 + wm * 64 + (lane >> 2);
    int cbase = n0 + wn * 48 + (lane & 3) * 2;
#pragma unroll
    for (int mi = 0; mi < 4; mi++) {
#pragma unroll
        for (int half = 0; half < 2; half++) {
            size_t row = (size_t)(rbase + mi * 16 + half * 8);
#pragma unroll
            for (int ni = 0; ni < 6; ni++) {
                int col = cbase + ni * 8;
                if (!NG || col + 1 < Nout) {
                    float v0 = c[mi][ni][half * 2 + 0];
                    float v1 = c[mi][ni][half * 2 + 1];
                    if (BIAS) { v0 += bias[col]; v1 += bias[col + 1]; }
                    if (GELU) { v0 = gelu_exact(v0); v1 = gelu_exact(v1); }
                    if (RES) {
                        v0 += resid[row * Nout + col];
                        v1 += resid[row * Nout + col + 1];
                    }
                    if (HALFOUT) {
                        *(__half2*)((__half*)Cout + row * Nout + col) =
                            __floats2half2_rn(v0, v1);
                    } else {
                        *(float2*)((float*)Cout + row * Nout + col) =
                            make_float2(v0, v1);
                    }
                }
            }
        }
    }
}

// ---------------- Host launcher ----------------
extern "C" void kernel_launch(void* const* d_in, const int* in_sizes, int n_in,
                              void* d_out, int out_size) {
    const float* x      = (const float*)d_in[0];
    const float* qkv_w  = (const float*)d_in[1];
    const float* scale  = (const float*)d_in[2];
    const float* out_w  = (const float*)d_in[3];
    const float* out_b  = (const float*)d_in[4];
    const float* ln1_w  = (const float*)d_in[5];
    const float* ln1_b  = (const float*)d_in[6];
    const float* ln2_w  = (const float*)d_in[7];
    const float* ln2_b  = (const float*)d_in[8];
    const float* fc1_w  = (const float*)d_in[9];
    const float* fc1_b  = (const float*)d_in[10];
    const float* fc2_w  = (const float*)d_in[11];
    const float* fc2_b  = (const float*)d_in[12];
    const float* norm_w = (const float*)d_in[13];
    const float* norm_b = (const float*)d_in[14];
    const float* head_w = (const float*)d_in[15];
    const float* head_b = (const float*)d_in[16];
    float* out = (float*)d_out;

    float  *h;
    __half *y, *qkv, *o, *m, *cls, *w16;
    cudaGetSymbolAddress((void**)&h,   g_h);
    cudaGetSymbolAddress((void**)&y,   g_y);
    cudaGetSymbolAddress((void**)&qkv, g_qkv);
    cudaGetSymbolAddress((void**)&o,   g_o);
    cudaGetSymbolAddress((void**)&m,   g_m);
    cudaGetSymbolAddress((void**)&cls, g_cls);
    cudaGetSymbolAddress((void**)&w16, g_w16);

    cudaMemcpyAsync(h, x, sizeof(float) * (size_t)RROWS * Dm, cudaMemcpyDeviceToDevice);

    convert_all<<<4096, 256>>>(qkv_w, out_w, fc1_w, fc2_w, head_w, w16);

    dim3 gQKV(3 * Dm / BN, RROWS / BM);   // (18, 248)
    dim3 gPROJ(Dm / BN, RROWS / BM);      // (6, 248)
    dim3 gFC1(FF / BN, RROWS / BM);       // (24, 248)
    dim3 gATT(Bz, Hh);
    int lnBlocks = RROWS / 8;

    for (int l = 0; l < Ll; l++) {
        const __half* qw = w16 + OQKV + (size_t)l * 3 * Dm * Dm;
        const __half* ow = w16 + OOUT + (size_t)l * Dm * Dm;
        const __half* w1 = w16 + OFC1 + (size_t)l * FF * Dm;
        const __half* w2 = w16 + OFC2 + (size_t)l * Dm * FF;

        ln_kernel<<<lnBlocks, 256>>>(h, ln1_w + l * Dm, ln1_b + l * Dm, y, RROWS, Dm);
        hgemm<false, false, false, true, false><<<gQKV, GT>>>(
            y, qw, nullptr, nullptr, qkv, RROWS, 3 * Dm, Dm);
        attn_kernel<<<gATT, 128>>>(qkv, scale + l * Hh, o);
        hgemm<true, true, false, false, false><<<gPROJ, GT>>>(
            o, ow, out_b + l * Dm, h, h, RROWS, Dm, Dm);
        ln_kernel<<<lnBlocks, 256>>>(h, ln2_w + l * Dm, ln2_b + l * Dm, y, RROWS, Dm);
        hgemm<true, false, true, true, false><<<gFC1, GT>>>(
            y, w1, fc1_b + l * FF, nullptr, m, RROWS, FF, Dm);
        hgemm<true, true, false, false, false><<<gPROJ, GT>>>(
            m, w2, fc2_b + l * Dm, h, h, RROWS, Dm, FF);
    }

    ln_kernel<<<Bz / 8, 256>>>(h, norm_w, norm_b, cls, Bz, (long long)Nt * Dm);
    dim3 gHEAD((NC + BN - 1) / BN, Bz / BM); // (11, 8)
    hgemm<true, false, false, false, true><<<gHEAD, GT>>>(
        cls, w16 + OHEAD, head_b, nullptr, out, Bz, NC, Dm);
}